// round 3
// baseline (speedup 1.0000x reference)
#include <cuda_runtime.h>
#include <math.h>

#define NTHREADS 256
#define HLEN     200
#define DIM      64

// smem layout in floats
#define OFF_HISTT 0        // [64][200] transposed history (d-major)
#define OFF_M     12800    // [64][64]  fused per-batch matrix
#define OFF_TGT   16896    // [64]
#define OFF_C     16960    // [64]      fused bias c_j
#define OFF_SC    17024    // [200]     scores -> softmax weights
#define OFF_RED   17224    // [256]
#define OFF_COMB  17480    // [192]
#define OFF_Z1    17672    // [128]
#define OFF_Z2    17800    // [64]
#define SMEM_FLOATS 17864
#define SMEM_BYTES  (SMEM_FLOATS * 4)

__global__ __launch_bounds__(NTHREADS, 2)
void din_kernel(const int*   __restrict__ item_ids,
                const int*   __restrict__ history,
                const int*   __restrict__ hist_len,
                const float* __restrict__ emb,
                const float* __restrict__ aW1,
                const float* __restrict__ ab1,
                const float* __restrict__ aW2,
                const float* __restrict__ fW1,
                const float* __restrict__ fb1,
                const float* __restrict__ fW2,
                const float* __restrict__ fb2,
                const float* __restrict__ fW3,
                const float* __restrict__ fb3,
                float*       __restrict__ out)
{
    extern __shared__ float sm[];
    float* histT  = sm + OFF_HISTT;
    float* M_s    = sm + OFF_M;
    float* tgt_s  = sm + OFF_TGT;
    float* c_s    = sm + OFF_C;
    float* sc_s   = sm + OFF_SC;
    float* red_s  = sm + OFF_RED;
    float* comb_s = sm + OFF_COMB;
    float* z1_s   = sm + OFF_Z1;
    float* z2_s   = sm + OFF_Z2;

    const int b    = blockIdx.x;
    const int tid  = threadIdx.x;
    const int lane = tid & 31;
    const int wid  = tid >> 5;

    // ---- S0: target embedding
    if (tid < 16) {
        int iid = item_ids[b];
        ((float4*)tgt_s)[tid] = ((const float4*)(emb + (size_t)iid * DIM))[tid];
    }
    __syncthreads();                                    // sync A

    const int hlen = hist_len[b];

    // ---- S1a: gather history -> transposed smem (zero rows past hlen)
    if (tid < HLEN) {
        const bool live = (tid < hlen);
        const float4* row = live
            ? (const float4*)(emb + (size_t)history[b * HLEN + tid] * DIM)
            : (const float4*)emb;
        #pragma unroll
        for (int c = 0; c < 16; c++) {
            float4 v = make_float4(0.f, 0.f, 0.f, 0.f);
            if (live) v = row[c];
            histT[(4*c+0) * HLEN + tid] = v.x;
            histT[(4*c+1) * HLEN + tid] = v.y;
            histT[(4*c+2) * HLEN + tid] = v.z;
            histT[(4*c+3) * HLEN + tid] = v.w;
        }
    }

    // ---- S1b: fused matrix M[d][j] = A1[d][j] + tgt[d]*A3[d][j]
    {
        const float4* A1 = (const float4*)aW1;                 // rows [0,64)
        const float4* A3 = (const float4*)(aW1 + 128 * DIM);   // rows [128,192)
        #pragma unroll
        for (int it = 0; it < 4; it++) {
            int cc = tid + it * NTHREADS;       // float4 chunk 0..1023
            int d  = cc >> 4;
            float t = tgt_s[d];
            float4 a1 = A1[cc], a3 = A3[cc], m;
            m.x = fmaf(t, a3.x, a1.x);
            m.y = fmaf(t, a3.y, a1.y);
            m.z = fmaf(t, a3.z, a1.z);
            m.w = fmaf(t, a3.w, a1.w);
            ((float4*)M_s)[cc] = m;
        }
    }

    // ---- S1c: c_j partials: sum_d tgt[d]*A2[d][j] over 16-d slice
    {
        int jj = tid & 63, g = tid >> 6;
        const float* A2 = aW1 + 64 * DIM;
        float p = 0.f;
        #pragma unroll
        for (int d = g * 16; d < g * 16 + 16; d++)
            p = fmaf(tgt_s[d], __ldg(A2 + d * DIM + jj), p);
        red_s[tid] = p;
    }
    __syncthreads();                                    // sync B

    // ---- S2: finalize c_j
    if (tid < DIM) {
        float c = __ldg(ab1 + tid) + red_s[tid] + red_s[64 + tid]
                + red_s[128 + tid] + red_s[192 + tid];
        c_s[tid] = c;
    }
    __syncthreads();                                    // sync C

    // ---- S3: scores GEMM. thread = (tl, tj): 8 rows x 8 cols register tile.
    //   tj = tid&7  -> j0 = 8*tj ;  tl = tid>>3 -> l0 = 8*tl  (tl<25 valid)
    // Threads with l0 >= hlen (or tl>=25) keep acc=0; their epilogue then
    // yields exactly the padded-row score sum_j relu(c_j)*w2_j. No fixup pass.
    {
        const int tj = tid & 7;
        const int tl = tid >> 3;
        const int j0 = tj << 3;
        const int l0 = tl << 3;

        float acc[8][8];
        #pragma unroll
        for (int i = 0; i < 8; i++)
            #pragma unroll
            for (int k = 0; k < 8; k++) acc[i][k] = 0.f;

        if (tl < 25 && l0 < hlen) {
            const float* hp = histT + l0;
            const float* mp = M_s + j0;
            #pragma unroll 2
            for (int d = 0; d < DIM; d++) {
                float4 h0 = *(const float4*)(hp + d * HLEN);
                float4 h1 = *(const float4*)(hp + d * HLEN + 4);
                float4 m0 = *(const float4*)(mp + (d << 6));
                float4 m1 = *(const float4*)(mp + (d << 6) + 4);
                float hv[8] = {h0.x, h0.y, h0.z, h0.w, h1.x, h1.y, h1.z, h1.w};
                float mv[8] = {m0.x, m0.y, m0.z, m0.w, m1.x, m1.y, m1.z, m1.w};
                #pragma unroll
                for (int i = 0; i < 8; i++)
                    #pragma unroll
                    for (int k = 0; k < 8; k++)
                        acc[i][k] = fmaf(hv[i], mv[k], acc[i][k]);
            }
        }

        // epilogue: s_i = sum_k relu(acc[i][k] + c_k) * w2_k, reduce over tj
        float4 cA = ((const float4*)c_s)[tj * 2];
        float4 cB = ((const float4*)c_s)[tj * 2 + 1];
        float4 wA = __ldg((const float4*)aW2 + tj * 2);
        float4 wB = __ldg((const float4*)aW2 + tj * 2 + 1);

        float s[8];
        #pragma unroll
        for (int i = 0; i < 8; i++) {
            float t0 = fmaxf(acc[i][0] + cA.x, 0.f) * wA.x;
            t0 = fmaf(fmaxf(acc[i][1] + cA.y, 0.f), wA.y, t0);
            t0 = fmaf(fmaxf(acc[i][2] + cA.z, 0.f), wA.z, t0);
            t0 = fmaf(fmaxf(acc[i][3] + cA.w, 0.f), wA.w, t0);
            t0 = fmaf(fmaxf(acc[i][4] + cB.x, 0.f), wB.x, t0);
            t0 = fmaf(fmaxf(acc[i][5] + cB.y, 0.f), wB.y, t0);
            t0 = fmaf(fmaxf(acc[i][6] + cB.z, 0.f), wB.z, t0);
            t0 = fmaf(fmaxf(acc[i][7] + cB.w, 0.f), wB.w, t0);
            s[i] = t0;
        }
        #pragma unroll
        for (int o = 1; o < 8; o <<= 1) {
            #pragma unroll
            for (int i = 0; i < 8; i++)
                s[i] += __shfl_xor_sync(0xffffffffu, s[i], o);
        }
        if (tj == 0 && tl < 25) {
            *(float4*)(sc_s + l0)     = make_float4(s[0], s[1], s[2], s[3]);
            *(float4*)(sc_s + l0 + 4) = make_float4(s[4], s[5], s[6], s[7]);
        }
    }
    __syncthreads();                                    // sync D

    // ---- S5: softmax over sc_s[0..199]
    {
        float v = (tid < HLEN) ? sc_s[tid] : -INFINITY;
        float m = v;
        #pragma unroll
        for (int o = 16; o; o >>= 1) m = fmaxf(m, __shfl_xor_sync(0xffffffffu, m, o));
        if (lane == 0) red_s[wid] = m;
        __syncthreads();
        float mm = red_s[0];
        #pragma unroll
        for (int w = 1; w < 8; w++) mm = fmaxf(mm, red_s[w]);

        float e = (tid < HLEN) ? __expf(v - mm) : 0.f;
        float ssum = e;
        #pragma unroll
        for (int o = 16; o; o >>= 1) ssum += __shfl_xor_sync(0xffffffffu, ssum, o);
        if (lane == 0) red_s[8 + wid] = ssum;
        __syncthreads();
        float tot = red_s[8];
        #pragma unroll
        for (int w = 1; w < 8; w++) tot += red_s[8 + w];
        float inv = 1.f / tot;
        if (tid < HLEN) sc_s[tid] = e * inv;
    }
    __syncthreads();

    // ---- S6: pooled[d] = sum_l w[l]*histT[d][l] (pads: hist=0 -> contribute 0)
    if (tid < 128) {
        int d = tid & 63, q = tid >> 6;         // two 100-long halves
        const float4* hp = (const float4*)(histT + d * HLEN + q * 100);
        const float4* wp = (const float4*)(sc_s + q * 100);
        float p0 = 0.f, p1 = 0.f;
        #pragma unroll 5
        for (int i = 0; i < 24; i += 2) {
            float4 h = hp[i], w = wp[i];
            p0 = fmaf(h.x, w.x, p0); p0 = fmaf(h.y, w.y, p0);
            p0 = fmaf(h.z, w.z, p0); p0 = fmaf(h.w, w.w, p0);
            float4 h2 = hp[i+1], w2 = wp[i+1];
            p1 = fmaf(h2.x, w2.x, p1); p1 = fmaf(h2.y, w2.y, p1);
            p1 = fmaf(h2.z, w2.z, p1); p1 = fmaf(h2.w, w2.w, p1);
        }
        { float4 h = hp[24], w = wp[24];
          p0 = fmaf(h.x, w.x, p0); p0 = fmaf(h.y, w.y, p0);
          p0 = fmaf(h.z, w.z, p0); p0 = fmaf(h.w, w.w, p0); }
        red_s[tid] = p0 + p1;
    }
    __syncthreads();
    if (tid < DIM) {
        float pooled = red_s[tid] + red_s[64 + tid];
        float tg = tgt_s[tid];
        comb_s[tid]        = tg;
        comb_s[64 + tid]   = pooled;
        comb_s[128 + tid]  = pooled - tg;
    }
    __syncthreads();

    // ---- S7: MLP head (multi-accumulator to break serial FMA chains)
    if (tid < 128) {
        float a0 = 0.f, a1 = 0.f, a2 = 0.f, a3 = 0.f;
        #pragma unroll 4
        for (int k = 0; k < 192; k += 4) {
            a0 = fmaf(comb_s[k+0], __ldg(fW1 + (k+0) * 128 + tid), a0);
            a1 = fmaf(comb_s[k+1], __ldg(fW1 + (k+1) * 128 + tid), a1);
            a2 = fmaf(comb_s[k+2], __ldg(fW1 + (k+2) * 128 + tid), a2);
            a3 = fmaf(comb_s[k+3], __ldg(fW1 + (k+3) * 128 + tid), a3);
        }
        z1_s[tid] = fmaxf((a0 + a1) + (a2 + a3) + __ldg(fb1 + tid), 0.f);
    }
    __syncthreads();
    if (tid < 64) {
        float a0 = 0.f, a1 = 0.f, a2 = 0.f, a3 = 0.f;
        #pragma unroll 4
        for (int k = 0; k < 128; k += 4) {
            a0 = fmaf(z1_s[k+0], __ldg(fW2 + (k+0) * 64 + tid), a0);
            a1 = fmaf(z1_s[k+1], __ldg(fW2 + (k+1) * 64 + tid), a1);
            a2 = fmaf(z1_s[k+2], __ldg(fW2 + (k+2) * 64 + tid), a2);
            a3 = fmaf(z1_s[k+3], __ldg(fW2 + (k+3) * 64 + tid), a3);
        }
        z2_s[tid] = fmaxf((a0 + a1) + (a2 + a3) + __ldg(fb2 + tid), 0.f);
    }
    __syncthreads();
    if (tid < 32) {
        float acc = fmaf(z2_s[tid], __ldg(fW3 + tid),
                         z2_s[tid + 32] * __ldg(fW3 + tid + 32));
        #pragma unroll
        for (int o = 16; o; o >>= 1) acc += __shfl_xor_sync(0xffffffffu, acc, o);
        if (tid == 0) {
            float zz = acc + __ldg(fb3);
            out[b] = 1.f / (1.f + __expf(-zz));
        }
    }
}

extern "C" void kernel_launch(void* const* d_in, const int* in_sizes, int n_in,
                              void* d_out, int out_size)
{
    const int*   item_ids = (const int*)  d_in[0];
    const int*   history  = (const int*)  d_in[1];
    const int*   hist_len = (const int*)  d_in[2];
    const float* emb      = (const float*)d_in[3];
    const float* aW1      = (const float*)d_in[4];
    const float* ab1      = (const float*)d_in[5];
    const float* aW2      = (const float*)d_in[6];
    // d_in[7] = ab2 — dropped (softmax shift-invariant)
    const float* fW1      = (const float*)d_in[8];
    const float* fb1      = (const float*)d_in[9];
    const float* fW2      = (const float*)d_in[10];
    const float* fb2      = (const float*)d_in[11];
    const float* fW3      = (const float*)d_in[12];
    const float* fb3      = (const float*)d_in[13];
    float* out = (float*)d_out;

    const int nb = in_sizes[0];

    cudaFuncSetAttribute(din_kernel, cudaFuncAttributeMaxDynamicSharedMemorySize, SMEM_BYTES);
    din_kernel<<<nb, NTHREADS, SMEM_BYTES>>>(
        item_ids, history, hist_len, emb,
        aW1, ab1, aW2, fW1, fb1, fW2, fb2, fW3, fb3, out);
}

// round 5
// speedup vs baseline: 1.1656x; 1.1656x over previous
#include <cuda_runtime.h>
#include <math.h>

#define NTHREADS 256
#define HLEN     200
#define HSTRIDE  208          // padded histT row stride (swizzle-safe, float4-aligned)
#define DIM      64

// smem layout in floats
#define OFF_HISTT 0                      // [64][208] transposed history, XOR-swizzled
#define OFF_M     13312                  // [64][64]
#define OFF_TGT   17408                  // [64]
#define OFF_C     17472                  // [64]
#define OFF_SC    17536                  // [200]
#define OFF_RED   17736                  // [256]
#define OFF_COMB  17992                  // [192]
#define OFF_Z1    18184                  // [128]
#define OFF_Z2    18312                  // [64]
#define OFF_HID   18376                  // [200] (int)
#define OFF_SPAD  18576                  // [1]
#define SMEM_FLOATS 18580
#define SMEM_BYTES  (SMEM_FLOATS * 4)

__global__ __launch_bounds__(NTHREADS, 3)
void din_kernel(const int*   __restrict__ item_ids,
                const int*   __restrict__ history,
                const int*   __restrict__ hist_len,
                const float* __restrict__ emb,
                const float* __restrict__ aW1,
                const float* __restrict__ ab1,
                const float* __restrict__ aW2,
                const float* __restrict__ fW1,
                const float* __restrict__ fb1,
                const float* __restrict__ fW2,
                const float* __restrict__ fb2,
                const float* __restrict__ fW3,
                const float* __restrict__ fb3,
                float*       __restrict__ out)
{
    extern __shared__ float sm[];
    float* histT  = sm + OFF_HISTT;
    float* M_s    = sm + OFF_M;
    float* tgt_s  = sm + OFF_TGT;
    float* c_s    = sm + OFF_C;
    float* sc_s   = sm + OFF_SC;
    float* red_s  = sm + OFF_RED;
    float* comb_s = sm + OFF_COMB;
    float* z1_s   = sm + OFF_Z1;
    float* z2_s   = sm + OFF_Z2;
    int*   hid_s  = (int*)(sm + OFF_HID);
    float* spad_s = sm + OFF_SPAD;

    const int b    = blockIdx.x;
    const int tid  = threadIdx.x;
    const int lane = tid & 31;
    const int wid  = tid >> 5;

    // ---- S0: history ids + target embedding
    if (tid < HLEN) hid_s[tid] = history[b * HLEN + tid];
    if (tid < 16) {
        int iid = item_ids[b];
        ((float4*)tgt_s)[tid] = ((const float4*)(emb + (size_t)iid * DIM))[tid];
    }
    __syncthreads();                                    // sync A

    const int hlen = hist_len[b];

    // ---- S1a: COALESCED gather -> swizzled transposed smem.
    // idx = row*16 + c : 16 threads cover one row's 256B (warp = 2 rows, 8 lines).
    // logical (d, l) lives at histT[d*HSTRIDE + (l ^ (((d>>2)&3)<<2))]
    for (int idx = tid; idx < HLEN * 16; idx += NTHREADS) {
        int row = idx >> 4;
        int c   = idx & 15;                       // float4 chunk = d>>2
        float4 v = make_float4(0.f, 0.f, 0.f, 0.f);
        if (row < hlen)
            v = ((const float4*)(emb + (size_t)hid_s[row] * DIM))[c];
        int rowx = row ^ ((c & 3) << 2);          // XOR swizzle
        float* dst = histT + (c << 2) * HSTRIDE + rowx;
        dst[0]           = v.x;
        dst[HSTRIDE]     = v.y;
        dst[2 * HSTRIDE] = v.z;
        dst[3 * HSTRIDE] = v.w;
    }

    // ---- S1b: fused matrix M[d][j] = A1[d][j] + tgt[d]*A3[d][j]
    {
        const float4* A1 = (const float4*)aW1;                 // rows [0,64)
        const float4* A3 = (const float4*)(aW1 + 128 * DIM);   // rows [128,192)
        #pragma unroll
        for (int it = 0; it < 4; it++) {
            int cc = tid + it * NTHREADS;       // float4 chunk 0..1023
            int d  = cc >> 4;
            float t = tgt_s[d];
            float4 a1 = A1[cc], a3 = A3[cc], m;
            m.x = fmaf(t, a3.x, a1.x);
            m.y = fmaf(t, a3.y, a1.y);
            m.z = fmaf(t, a3.z, a1.z);
            m.w = fmaf(t, a3.w, a1.w);
            ((float4*)M_s)[cc] = m;
        }
    }

    // ---- S1c: c_j partials: sum_d tgt[d]*A2[d][j] over 16-d slice
    {
        int jj = tid & 63, g = tid >> 6;
        const float* A2 = aW1 + 64 * DIM;
        float p = 0.f;
        #pragma unroll
        for (int d = g * 16; d < g * 16 + 16; d++)
            p = fmaf(tgt_s[d], __ldg(A2 + d * DIM + jj), p);
        red_s[tid] = p;
    }
    __syncthreads();                                    // sync B

    // ---- S2: finalize c_j; stage relu(c)*w2 for s_pad
    if (tid < DIM) {
        float c = __ldg(ab1 + tid) + red_s[tid] + red_s[64 + tid]
                + red_s[128 + tid] + red_s[192 + tid];
        c_s[tid]  = c;
        z1_s[tid] = fmaxf(c, 0.f) * __ldg(aW2 + tid);
    }
    __syncthreads();                                    // sync C

    // ---- S3a: warp 0 reduces s_pad (others proceed into GEMM)
    if (wid == 0) {
        float v = z1_s[lane] + z1_s[lane + 32];
        #pragma unroll
        for (int o = 16; o; o >>= 1) v += __shfl_xor_sync(0xffffffffu, v, o);
        if (lane == 0) spad_s[0] = v;
    }

    // ---- S3b: scores GEMM. thread = (tl, tj): 4 rows x 4 cols tile.
    // tj = tid&15 (j0=4tj), tl = tid>>4 (l0 = l_base + 4tl).
    // `l0 < HLEN` is warp-uniform (each warp's two l0 values never straddle 200).
    const int tj = tid & 15;
    const int tl = tid >> 4;
    const int j0 = tj << 2;
    const float4 w2v = __ldg((const float4*)aW2 + tj);
    const float4 c4  = ((const float4*)c_s)[tj];

    for (int l_base = 0; l_base < hlen; l_base += 64) {
        int l0 = l_base + (tl << 2);
        if (l0 < HLEN) {
            float acc[4][4];
            #pragma unroll
            for (int i = 0; i < 4; i++)
                #pragma unroll
                for (int k = 0; k < 4; k++) acc[i][k] = 0.f;

            #pragma unroll 4
            for (int d4 = 0; d4 < 16; d4++) {
                const int xm = (d4 & 3) << 2;
                const float* hb = histT + (l0 ^ xm) + (d4 << 2) * HSTRIDE;
                const float* mb = M_s + j0 + (d4 << 8);
                #pragma unroll
                for (int kk = 0; kk < 4; kk++) {
                    float4 h = *(const float4*)(hb + kk * HSTRIDE);
                    float4 m = *(const float4*)(mb + (kk << 6));
                    acc[0][0] = fmaf(h.x, m.x, acc[0][0]);
                    acc[0][1] = fmaf(h.x, m.y, acc[0][1]);
                    acc[0][2] = fmaf(h.x, m.z, acc[0][2]);
                    acc[0][3] = fmaf(h.x, m.w, acc[0][3]);
                    acc[1][0] = fmaf(h.y, m.x, acc[1][0]);
                    acc[1][1] = fmaf(h.y, m.y, acc[1][1]);
                    acc[1][2] = fmaf(h.y, m.z, acc[1][2]);
                    acc[1][3] = fmaf(h.y, m.w, acc[1][3]);
                    acc[2][0] = fmaf(h.z, m.x, acc[2][0]);
                    acc[2][1] = fmaf(h.z, m.y, acc[2][1]);
                    acc[2][2] = fmaf(h.z, m.z, acc[2][2]);
                    acc[2][3] = fmaf(h.z, m.w, acc[2][3]);
                    acc[3][0] = fmaf(h.w, m.x, acc[3][0]);
                    acc[3][1] = fmaf(h.w, m.y, acc[3][1]);
                    acc[3][2] = fmaf(h.w, m.z, acc[3][2]);
                    acc[3][3] = fmaf(h.w, m.w, acc[3][3]);
                }
            }

            float s[4];
            #pragma unroll
            for (int i = 0; i < 4; i++) {
                float t0 = fmaxf(acc[i][0] + c4.x, 0.f) * w2v.x;
                t0 = fmaf(fmaxf(acc[i][1] + c4.y, 0.f), w2v.y, t0);
                t0 = fmaf(fmaxf(acc[i][2] + c4.z, 0.f), w2v.z, t0);
                t0 = fmaf(fmaxf(acc[i][3] + c4.w, 0.f), w2v.w, t0);
                s[i] = t0;
            }
            // reduce over 16 tj lanes (xor<16 stays within same-tl half-warp)
            #pragma unroll
            for (int o = 1; o < 16; o <<= 1) {
                s[0] += __shfl_xor_sync(0xffffffffu, s[0], o);
                s[1] += __shfl_xor_sync(0xffffffffu, s[1], o);
                s[2] += __shfl_xor_sync(0xffffffffu, s[2], o);
                s[3] += __shfl_xor_sync(0xffffffffu, s[3], o);
            }
            if (tj == 0)
                *(float4*)(sc_s + l0) = make_float4(s[0], s[1], s[2], s[3]);
        }
    }
    __syncthreads();                                    // sync D

    // ---- S4: padded-row scores = s_pad for rows in unvisited 64-blocks
    {
        float sp = spad_s[0];
        int filled = (hlen + 63) & ~63;
        if (filled > HLEN) filled = HLEN;
        for (int l = filled + tid; l < HLEN; l += NTHREADS) sc_s[l] = sp;
    }
    __syncthreads();                                    // sync E

    // ---- S5: softmax over sc_s[0..199]
    {
        float v = (tid < HLEN) ? sc_s[tid] : -INFINITY;
        float m = v;
        #pragma unroll
        for (int o = 16; o; o >>= 1) m = fmaxf(m, __shfl_xor_sync(0xffffffffu, m, o));
        if (lane == 0) red_s[wid] = m;
        __syncthreads();
        float mm = red_s[0];
        #pragma unroll
        for (int w = 1; w < 8; w++) mm = fmaxf(mm, red_s[w]);

        float e = (tid < HLEN) ? __expf(v - mm) : 0.f;
        float ssum = e;
        #pragma unroll
        for (int o = 16; o; o >>= 1) ssum += __shfl_xor_sync(0xffffffffu, ssum, o);
        if (lane == 0) red_s[8 + wid] = ssum;
        __syncthreads();
        float tot = red_s[8];
        #pragma unroll
        for (int w = 1; w < 8; w++) tot += red_s[8 + w];
        float inv = 1.f / tot;
        if (tid < HLEN) sc_s[tid] = e * inv;
    }
    __syncthreads();

    // ---- S6: pooled[d] = sum_l w[l]*hist[l][d]  (swizzled reads; pads are 0)
    if (tid < 128) {
        int d = tid & 63, q = tid >> 6;
        int xm = ((d >> 2) & 3) << 2;
        const float* hb = histT + d * HSTRIDE;
        const float* wb = sc_s + q * 100;
        float p0 = 0.f, p1 = 0.f;
        #pragma unroll 5
        for (int i = 0; i < 25; i++) {
            int l0 = q * 100 + 4 * i;
            float4 h = *(const float4*)(hb + (l0 ^ xm));
            float4 w = *(const float4*)(wb + 4 * i);
            p0 = fmaf(h.x, w.x, p0); p1 = fmaf(h.y, w.y, p1);
            p0 = fmaf(h.z, w.z, p0); p1 = fmaf(h.w, w.w, p1);
        }
        red_s[tid] = p0 + p1;
    }
    __syncthreads();
    if (tid < DIM) {
        float pooled = red_s[tid] + red_s[64 + tid];
        float tg = tgt_s[tid];
        comb_s[tid]        = tg;
        comb_s[64 + tid]   = pooled;
        comb_s[128 + tid]  = pooled - tg;
    }
    __syncthreads();

    // ---- S7: MLP head (multi-accumulator)
    if (tid < 128) {
        float a0 = 0.f, a1 = 0.f, a2 = 0.f, a3 = 0.f;
        #pragma unroll 4
        for (int k = 0; k < 192; k += 4) {
            a0 = fmaf(comb_s[k+0], __ldg(fW1 + (k+0) * 128 + tid), a0);
            a1 = fmaf(comb_s[k+1], __ldg(fW1 + (k+1) * 128 + tid), a1);
            a2 = fmaf(comb_s[k+2], __ldg(fW1 + (k+2) * 128 + tid), a2);
            a3 = fmaf(comb_s[k+3], __ldg(fW1 + (k+3) * 128 + tid), a3);
        }
        z1_s[tid] = fmaxf((a0 + a1) + (a2 + a3) + __ldg(fb1 + tid), 0.f);
    }
    __syncthreads();
    if (tid < 64) {
        float a0 = 0.f, a1 = 0.f, a2 = 0.f, a3 = 0.f;
        #pragma unroll 4
        for (int k = 0; k < 128; k += 4) {
            a0 = fmaf(z1_s[k+0], __ldg(fW2 + (k+0) * 64 + tid), a0);
            a1 = fmaf(z1_s[k+1], __ldg(fW2 + (k+1) * 64 + tid), a1);
            a2 = fmaf(z1_s[k+2], __ldg(fW2 + (k+2) * 64 + tid), a2);
            a3 = fmaf(z1_s[k+3], __ldg(fW2 + (k+3) * 64 + tid), a3);
        }
        z2_s[tid] = fmaxf((a0 + a1) + (a2 + a3) + __ldg(fb2 + tid), 0.f);
    }
    __syncthreads();
    if (tid < 32) {
        float acc = fmaf(z2_s[tid], __ldg(fW3 + tid),
                         z2_s[tid + 32] * __ldg(fW3 + tid + 32));
        #pragma unroll
        for (int o = 16; o; o >>= 1) acc += __shfl_xor_sync(0xffffffffu, acc, o);
        if (tid == 0) {
            float zz = acc + __ldg(fb3);
            out[b] = 1.f / (1.f + __expf(-zz));
        }
    }
}

extern "C" void kernel_launch(void* const* d_in, const int* in_sizes, int n_in,
                              void* d_out, int out_size)
{
    const int*   item_ids = (const int*)  d_in[0];
    const int*   history  = (const int*)  d_in[1];
    const int*   hist_len = (const int*)  d_in[2];
    const float* emb      = (const float*)d_in[3];
    const float* aW1      = (const float*)d_in[4];
    const float* ab1      = (const float*)d_in[5];
    const float* aW2      = (const float*)d_in[6];
    // d_in[7] = ab2 — dropped (softmax shift-invariant)
    const float* fW1      = (const float*)d_in[8];
    const float* fb1      = (const float*)d_in[9];
    const float* fW2      = (const float*)d_in[10];
    const float* fb2      = (const float*)d_in[11];
    const float* fW3      = (const float*)d_in[12];
    const float* fb3      = (const float*)d_in[13];
    float* out = (float*)d_out;

    const int nb = in_sizes[0];

    cudaFuncSetAttribute(din_kernel, cudaFuncAttributeMaxDynamicSharedMemorySize, SMEM_BYTES);
    din_kernel<<<nb, NTHREADS, SMEM_BYTES>>>(
        item_ids, history, hist_len, emb,
        aW1, ab1, aW2, fW1, fb1, fW2, fb2, fW3, fb3, out);
}

// round 7
// speedup vs baseline: 1.2527x; 1.0747x over previous
#include <cuda_runtime.h>
#include <cuda_bf16.h>
#include <math.h>

#define NTHREADS 256
#define HLEN     200
#define AROWS    208           // 13 m16-tiles
#define DIM      64

// ---- dynamic smem layout (bytes) ----
// bf16 tiles: 128B rows, chunk-XOR swizzle: byte(row,chunk)=row*128+((chunk^(row&7))<<4)
#define AHI_OFF   0                      // hist hi: 208 x 64 bf16 = 26624 B
#define ALO_OFF   26624                  // hist lo: 26624 B
#define BHI_OFF   53248                  // M hi: 64 x 64 bf16 = 8192 B
#define BLO_OFF   61440                  // M lo: 8192 B
#define FBASE     69632                  // fp32 region (floats below)
#define F_TGT   (FBASE/4 + 0)            // 64
#define F_C     (F_TGT + 64)             // 64
#define F_W2    (F_C + 64)               // 64
#define F_SC    (F_W2 + 64)              // 200
#define F_RED   (F_SC + 200)             // 512
#define F_COMB  (F_RED + 512)            // 192
#define F_Z1    (F_COMB + 192)           // 128
#define F_Z2    (F_Z1 + 128)             // 64
#define F_HID   (F_Z2 + 64)              // 200 (int)
#define F_SPAD  (F_HID + 200)            // 1
#define SMEM_FLOATS (F_SPAD + 1)
#define SMEM_BYTES  (SMEM_FLOATS * 4)

__device__ __forceinline__ unsigned smem_u32(const void* p) {
    unsigned a;
    asm("{ .reg .u64 t; cvta.to.shared.u64 t, %1; cvt.u32.u64 %0, t; }"
        : "=r"(a) : "l"(p));
    return a;
}

#define LDSM_X4(r0, r1, r2, r3, addr) \
    asm volatile("ldmatrix.sync.aligned.m8n8.x4.shared.b16 {%0,%1,%2,%3}, [%4];" \
        : "=r"(r0), "=r"(r1), "=r"(r2), "=r"(r3) : "r"(addr))

#define LDSM_X2T(r0, r1, addr) \
    asm volatile("ldmatrix.sync.aligned.m8n8.x2.trans.shared.b16 {%0,%1}, [%2];" \
        : "=r"(r0), "=r"(r1) : "r"(addr))

#define MMA_BF16(d0, d1, d2, d3, a0, a1, a2, a3, b0, b1) \
    asm volatile("mma.sync.aligned.m16n8k16.row.col.f32.bf16.bf16.f32 " \
        "{%0,%1,%2,%3}, {%4,%5,%6,%7}, {%8,%9}, {%0,%1,%2,%3};" \
        : "+f"(d0), "+f"(d1), "+f"(d2), "+f"(d3) \
        : "r"(a0), "r"(a1), "r"(a2), "r"(a3), "r"(b0), "r"(b1))

__global__ __launch_bounds__(NTHREADS, 3)
void din_kernel(const int*   __restrict__ item_ids,
                const int*   __restrict__ history,
                const int*   __restrict__ hist_len,
                const float* __restrict__ emb,
                const float* __restrict__ aW1,
                const float* __restrict__ ab1,
                const float* __restrict__ aW2,
                const float* __restrict__ fW1,
                const float* __restrict__ fb1,
                const float* __restrict__ fW2,
                const float* __restrict__ fb2,
                const float* __restrict__ fW3,
                const float* __restrict__ fb3,
                float*       __restrict__ out)
{
    extern __shared__ float sm[];
    char*  smc    = (char*)sm;
    float* tgt_s  = sm + F_TGT;
    float* c_s    = sm + F_C;
    float* w2_s   = sm + F_W2;
    float* sc_s   = sm + F_SC;
    float* red_s  = sm + F_RED;
    float* comb_s = sm + F_COMB;
    float* z1_s   = sm + F_Z1;
    float* z2_s   = sm + F_Z2;
    int*   hid_s  = (int*)(sm + F_HID);
    float* spad_s = sm + F_SPAD;

    const int b    = blockIdx.x;
    const int tid  = threadIdx.x;
    const int lane = tid & 31;
    const int wid  = tid >> 5;
    const unsigned sbase = smem_u32(sm);

    // ---- S0: history ids + target embedding + w2
    if (tid < HLEN) hid_s[tid] = history[b * HLEN + tid];
    if (tid < 16) {
        int iid = item_ids[b];
        ((float4*)tgt_s)[tid] = ((const float4*)(emb + (size_t)iid * DIM))[tid];
    }
    if (tid < DIM) w2_s[tid] = __ldg(aW2 + tid);
    __syncthreads();                                    // sync A

    const int hlen = hist_len[b];

    // ---- S1a: coalesced gather -> bf16 hi/lo tiles, row-major, swizzled.
    // idx = row*16 + c: 16 fp32-float4 lanes per row. rows >= hlen (and up to 208) zeroed.
    for (int idx = tid; idx < AROWS * 16; idx += NTHREADS) {
        int row = idx >> 4;
        int c   = idx & 15;
        float4 v = make_float4(0.f, 0.f, 0.f, 0.f);
        if (row < hlen)
            v = ((const float4*)(emb + (size_t)hid_s[row] * DIM))[c];
        __nv_bfloat162 h01 = __floats2bfloat162_rn(v.x, v.y);
        __nv_bfloat162 h23 = __floats2bfloat162_rn(v.z, v.w);
        float lx = v.x - __bfloat162float(h01.x);
        float ly = v.y - __bfloat162float(h01.y);
        float lz = v.z - __bfloat162float(h23.x);
        float lw = v.w - __bfloat162float(h23.y);
        __nv_bfloat162 l01 = __floats2bfloat162_rn(lx, ly);
        __nv_bfloat162 l23 = __floats2bfloat162_rn(lz, lw);
        // byte offset: chunk = c>>1, 8B half = (c&1)*8
        int byteoff = row * 128 + (((c >> 1) ^ (row & 7)) << 4) + (c & 1) * 8;
        uint2 hh = make_uint2(*(unsigned*)&h01, *(unsigned*)&h23);
        uint2 ll = make_uint2(*(unsigned*)&l01, *(unsigned*)&l23);
        *(uint2*)(smc + AHI_OFF + byteoff) = hh;
        *(uint2*)(smc + ALO_OFF + byteoff) = ll;
    }

    // ---- S1b: B tiles (M[d][j] = A1[d][j] + tgt[d]*A3[d][j]) bf16 hi/lo, swizzled.
    // thread = (d, jq): d = tid>>2, j = jq*16 + [0,16)
    {
        int d  = tid >> 2;
        int jq = tid & 3;
        float t = tgt_s[d];
        const float* r1 = aW1 + d * DIM;
        const float* r3 = aW1 + (128 + d) * DIM;
        #pragma unroll
        for (int i = 0; i < 8; i++) {
            int j = jq * 16 + i * 2;
            float m0 = fmaf(t, __ldg(r3 + j),     __ldg(r1 + j));
            float m1 = fmaf(t, __ldg(r3 + j + 1), __ldg(r1 + j + 1));
            __nv_bfloat162 h = __floats2bfloat162_rn(m0, m1);
            float l0f = m0 - __bfloat162float(h.x);
            float l1f = m1 - __bfloat162float(h.y);
            __nv_bfloat162 l = __floats2bfloat162_rn(l0f, l1f);
            // byte = d*128 + swz(chunk = 2*jq + (i>>2)) + (i&3)*4
            int byteoff = d * 128 + ((((jq << 1) + (i >> 2)) ^ (d & 7)) << 4) + (i & 3) * 4;
            *(unsigned*)(smc + BHI_OFF + byteoff) = *(unsigned*)&h;
            *(unsigned*)(smc + BLO_OFF + byteoff) = *(unsigned*)&l;
        }
    }

    // ---- S1c: c_j partials: sum_d tgt[d]*A2[d][j] over 16-d slice
    {
        int jj = tid & 63, g = tid >> 6;
        const float* A2 = aW1 + 64 * DIM;
        float p = 0.f;
        #pragma unroll
        for (int d = g * 16; d < g * 16 + 16; d++)
            p = fmaf(tgt_s[d], __ldg(A2 + d * DIM + jj), p);
        red_s[tid] = p;
    }
    __syncthreads();                                    // sync B

    // ---- S2: finalize c_j; stage relu(c)*w2 for s_pad
    if (tid < DIM) {
        float c = __ldg(ab1 + tid) + red_s[tid] + red_s[64 + tid]
                + red_s[128 + tid] + red_s[192 + tid];
        c_s[tid]  = c;
        z1_s[tid] = fmaxf(c, 0.f) * w2_s[tid];
    }
    __syncthreads();                                    // sync C

    // ---- S3a: warp 0 reduces s_pad
    if (wid == 0) {
        float v = z1_s[lane] + z1_s[lane + 32];
        #pragma unroll
        for (int o = 16; o; o >>= 1) v += __shfl_xor_sync(0xffffffffu, v, o);
        if (lane == 0) spad_s[0] = v;
    }

    // ---- S3b: scores GEMM on tensor pipe (mma.sync bf16, 3-term hi/lo split).
    // Warp w handles m16-tiles mt = w, w+8, ... among live tiles.
    {
        const int nt = min(13, (hlen + 15) >> 4);
        const int m_off = ((lane >> 3) & 1) * 8 + (lane & 7);
        const int khalf = lane >> 4;
        const int bko   = ((lane >> 3) & 1) * 8 + (lane & 7);  // B row offset (lanes 0-15 used)

        for (int mt = wid; mt < nt; mt += 8) {
            // A fragments for 4 k-steps, hi and lo
            unsigned aH[4][4], aL[4][4];
            const int r = mt * 16 + m_off;
            #pragma unroll
            for (int k = 0; k < 4; k++) {
                unsigned ad = sbase + AHI_OFF + r * 128 + ((((k << 1) + khalf) ^ (r & 7)) << 4);
                LDSM_X4(aH[k][0], aH[k][1], aH[k][2], aH[k][3], ad);
                LDSM_X4(aL[k][0], aL[k][1], aL[k][2], aL[k][3], ad + (ALO_OFF - AHI_OFF));
            }

            float s0 = 0.f, s1 = 0.f;
            #pragma unroll
            for (int n = 0; n < 8; n++) {
                float d0 = 0.f, d1 = 0.f, d2 = 0.f, d3 = 0.f;
                #pragma unroll
                for (int k = 0; k < 4; k++) {
                    int drow = k * 16 + bko;
                    unsigned bd = sbase + BHI_OFF + drow * 128 + ((n ^ (drow & 7)) << 4);
                    unsigned bh0, bh1, bl0, bl1;
                    LDSM_X2T(bh0, bh1, bd);
                    LDSM_X2T(bl0, bl1, bd + (BLO_OFF - BHI_OFF));
                    MMA_BF16(d0, d1, d2, d3, aH[k][0], aH[k][1], aH[k][2], aH[k][3], bh0, bh1);
                    MMA_BF16(d0, d1, d2, d3, aH[k][0], aH[k][1], aH[k][2], aH[k][3], bl0, bl1);
                    MMA_BF16(d0, d1, d2, d3, aL[k][0], aL[k][1], aL[k][2], aL[k][3], bh0, bh1);
                }
                int j0 = n * 8 + 2 * (lane & 3);
                float c0 = c_s[j0], c1 = c_s[j0 + 1];
                float w0 = w2_s[j0], w1 = w2_s[j0 + 1];
                s0 = fmaf(fmaxf(d0 + c0, 0.f), w0, s0);
                s0 = fmaf(fmaxf(d1 + c1, 0.f), w1, s0);
                s1 = fmaf(fmaxf(d2 + c0, 0.f), w0, s1);
                s1 = fmaf(fmaxf(d3 + c1, 0.f), w1, s1);
            }
            // reduce over the 4 lanes sharing a row
            s0 += __shfl_xor_sync(0xffffffffu, s0, 1);
            s0 += __shfl_xor_sync(0xffffffffu, s0, 2);
            s1 += __shfl_xor_sync(0xffffffffu, s1, 1);
            s1 += __shfl_xor_sync(0xffffffffu, s1, 2);
            if ((lane & 3) == 0) {
                int l = mt * 16 + (lane >> 2);
                if (l < HLEN)     sc_s[l]     = s0;
                if (l + 8 < HLEN) sc_s[l + 8] = s1;
            }
        }
    }
    __syncthreads();                                    // sync D

    // ---- S4: fill rows beyond the live tiles with s_pad
    {
        float sp = spad_s[0];
        int filled = min(13, (hlen + 15) >> 4) * 16;
        for (int l = filled + tid; l < HLEN; l += NTHREADS) sc_s[l] = sp;
    }
    __syncthreads();                                    // sync E

    // ---- S5: softmax over sc_s[0..199]
    {
        float v = (tid < HLEN) ? sc_s[tid] : -INFINITY;
        float m = v;
        #pragma unroll
        for (int o = 16; o; o >>= 1) m = fmaxf(m, __shfl_xor_sync(0xffffffffu, m, o));
        if (lane == 0) red_s[wid] = m;
        __syncthreads();
        float mm = red_s[0];
        #pragma unroll
        for (int w = 1; w < 8; w++) mm = fmaxf(mm, red_s[w]);

        float e = (tid < HLEN) ? __expf(v - mm) : 0.f;
        float ssum = e;
        #pragma unroll
        for (int o = 16; o; o >>= 1) ssum += __shfl_xor_sync(0xffffffffu, ssum, o);
        if (lane == 0) red_s[8 + wid] = ssum;
        __syncthreads();
        float tot = red_s[8];
        #pragma unroll
        for (int w = 1; w < 8; w++) tot += red_s[8 + w];
        float inv = 1.f / tot;
        if (tid < HLEN) sc_s[tid] = e * inv;
    }
    __syncthreads();

    // ---- S6: pooled[d] = sum_l w[l]*(hi+lo)[l][d]; warp w covers 25 l-rows,
    // lane dp covers d = 2dp, 2dp+1. Conflict-free swizzled row reads.
    {
        float p0 = 0.f, p1 = 0.f;
        int dp = lane;
        #pragma unroll 5
        for (int i = 0; i < 25; i++) {
            int l = wid * 25 + i;
            float w = sc_s[l];
            int byteoff = l * 128 + (((dp >> 2) ^ (l & 7)) << 4) + (dp & 3) * 4;
            float2 h  = __bfloat1622float2(*(__nv_bfloat162*)(smc + AHI_OFF + byteoff));
            float2 lo = __bfloat1622float2(*(__nv_bfloat162*)(smc + ALO_OFF + byteoff));
            p0 = fmaf(w, h.x + lo.x, p0);
            p1 = fmaf(w, h.y + lo.y, p1);
        }
        red_s[wid * 64 + 2 * dp]     = p0;
        red_s[wid * 64 + 2 * dp + 1] = p1;
    }
    __syncthreads();
    if (tid < DIM) {
        float pooled = 0.f;
        #pragma unroll
        for (int w = 0; w < 8; w++) pooled += red_s[w * 64 + tid];
        float tg = tgt_s[tid];
        comb_s[tid]        = tg;
        comb_s[64 + tid]   = pooled;
        comb_s[128 + tid]  = pooled - tg;
    }
    __syncthreads();

    // ---- S7: MLP head
    if (tid < 128) {
        float a0 = 0.f, a1 = 0.f, a2 = 0.f, a3 = 0.f;
        #pragma unroll 4
        for (int k = 0; k < 192; k += 4) {
            a0 = fmaf(comb_s[k+0], __ldg(fW1 + (k+0) * 128 + tid), a0);
            a1 = fmaf(comb_s[k+1], __ldg(fW1 + (k+1) * 128 + tid), a1);
            a2 = fmaf(comb_s[k+2], __ldg(fW1 + (k+2) * 128 + tid), a2);
            a3 = fmaf(comb_s[k+3], __ldg(fW1 + (k+3) * 128 + tid), a3);
        }
        z1_s[tid] = fmaxf((a0 + a1) + (a2 + a3) + __ldg(fb1 + tid), 0.f);
    }
    __syncthreads();
    if (tid < 64) {
        float a0 = 0.f, a1 = 0.f, a2 = 0.f, a3 = 0.f;
        #pragma unroll 4
        for (int k = 0; k < 128; k += 4) {
            a0 = fmaf(z1_s[k+0], __ldg(fW2 + (k+0) * 64 + tid), a0);
            a1 = fmaf(z1_s[k+1], __ldg(fW2 + (k+1) * 64 + tid), a1);
            a2 = fmaf(z1_s[k+2], __ldg(fW2 + (k+2) * 64 + tid), a2);
            a3 = fmaf(z1_s[k+3], __ldg(fW2 + (k+3) * 64 + tid), a3);
        }
        z2_s[tid] = fmaxf((a0 + a1) + (a2 + a3) + __ldg(fb2 + tid), 0.f);
    }
    __syncthreads();
    if (tid < 32) {
        float acc = fmaf(z2_s[tid], __ldg(fW3 + tid),
                         z2_s[tid + 32] * __ldg(fW3 + tid + 32));
        #pragma unroll
        for (int o = 16; o; o >>= 1) acc += __shfl_xor_sync(0xffffffffu, acc, o);
        if (tid == 0) {
            float zz = acc + __ldg(fb3);
            out[b] = 1.f / (1.f + __expf(-zz));
        }
    }
}

extern "C" void kernel_launch(void* const* d_in, const int* in_sizes, int n_in,
                              void* d_out, int out_size)
{
    const int*   item_ids = (const int*)  d_in[0];
    const int*   history  = (const int*)  d_in[1];
    const int*   hist_len = (const int*)  d_in[2];
    const float* emb      = (const float*)d_in[3];
    const float* aW1      = (const float*)d_in[4];
    const float* ab1      = (const float*)d_in[5];
    const float* aW2      = (const float*)d_in[6];
    // d_in[7] = ab2 — dropped (softmax shift-invariant)
    const float* fW1      = (const float*)d_in[8];
    const float* fb1      = (const float*)d_in[9];
    const float* fW2      = (const float*)d_in[10];
    const float* fb2      = (const float*)d_in[11];
    const float* fW3      = (const float*)d_in[12];
    const float* fb3      = (const float*)d_in[13];
    float* out = (float*)d_out;

    const int nb = in_sizes[0];

    cudaFuncSetAttribute(din_kernel, cudaFuncAttributeMaxDynamicSharedMemorySize, SMEM_BYTES);
    din_kernel<<<nb, NTHREADS, SMEM_BYTES>>>(
        item_ids, history, hist_len, emb,
        aW1, ab1, aW2, fW1, fb1, fW2, fb2, fW3, fb3, out);
}

// round 8
// speedup vs baseline: 1.5311x; 1.2222x over previous
#include <cuda_runtime.h>
#include <cuda_bf16.h>
#include <math.h>

#define NTHREADS 256
#define HLEN     200
#define AROWS    208           // 13 m16-tiles
#define DIM      64
#define MAXB     4096

// ---- K1 dynamic smem layout (bytes) ----
// bf16 tiles: 128B rows, chunk-XOR swizzle: byte(row,chunk)=row*128+((chunk^(row&7))<<4)
#define AHI_OFF   0                      // hist hi: 208 x 64 bf16 = 26624 B
#define ALO_OFF   26624                  // hist lo: 26624 B
#define BHI_OFF   53248                  // M hi: 64 x 64 bf16 = 8192 B
#define BLO_OFF   61440                  // M lo: 8192 B
#define FBASE     69632                  // fp32 region (floats below)
#define F_TGT   (FBASE/4 + 0)            // 64
#define F_C     (F_TGT + 64)             // 64
#define F_W2    (F_C + 64)               // 64
#define F_SC    (F_W2 + 64)              // 200
#define F_RED   (F_SC + 200)             // 512
#define F_HID   (F_RED + 512)            // 200 (int)
#define F_SPAD  (F_HID + 200)            // 1
#define SMEM_FLOATS (F_SPAD + 1)
#define SMEM_BYTES  (SMEM_FLOATS * 4)

// inter-kernel scratch: comb = [tgt, pooled, pooled - tgt] per batch row
__device__ float g_comb[MAXB * 192];

__device__ __forceinline__ unsigned smem_u32(const void* p) {
    unsigned a;
    asm("{ .reg .u64 t; cvta.to.shared.u64 t, %1; cvt.u32.u64 %0, t; }"
        : "=r"(a) : "l"(p));
    return a;
}

#define LDSM_X4(r0, r1, r2, r3, addr) \
    asm volatile("ldmatrix.sync.aligned.m8n8.x4.shared.b16 {%0,%1,%2,%3}, [%4];" \
        : "=r"(r0), "=r"(r1), "=r"(r2), "=r"(r3) : "r"(addr))

#define LDSM_X2T(r0, r1, addr) \
    asm volatile("ldmatrix.sync.aligned.m8n8.x2.trans.shared.b16 {%0,%1}, [%2];" \
        : "=r"(r0), "=r"(r1) : "r"(addr))

#define MMA_BF16(d0, d1, d2, d3, a0, a1, a2, a3, b0, b1) \
    asm volatile("mma.sync.aligned.m16n8k16.row.col.f32.bf16.bf16.f32 " \
        "{%0,%1,%2,%3}, {%4,%5,%6,%7}, {%8,%9}, {%0,%1,%2,%3};" \
        : "+f"(d0), "+f"(d1), "+f"(d2), "+f"(d3) \
        : "r"(a0), "r"(a1), "r"(a2), "r"(a3), "r"(b0), "r"(b1))

__global__ __launch_bounds__(NTHREADS, 3)
void din_kernel(const int*   __restrict__ item_ids,
                const int*   __restrict__ history,
                const int*   __restrict__ hist_len,
                const float* __restrict__ emb,
                const float* __restrict__ aW1,
                const float* __restrict__ ab1,
                const float* __restrict__ aW2)
{
    extern __shared__ float sm[];
    char*  smc    = (char*)sm;
    float* tgt_s  = sm + F_TGT;
    float* c_s    = sm + F_C;
    float* w2_s   = sm + F_W2;
    float* sc_s   = sm + F_SC;
    float* red_s  = sm + F_RED;
    int*   hid_s  = (int*)(sm + F_HID);
    float* spad_s = sm + F_SPAD;

    const int b    = blockIdx.x;
    const int tid  = threadIdx.x;
    const int lane = tid & 31;
    const int wid  = tid >> 5;
    const unsigned sbase = smem_u32(sm);

    // ---- S0: history ids + target embedding + w2
    if (tid < HLEN) hid_s[tid] = history[b * HLEN + tid];
    if (tid < 16) {
        int iid = item_ids[b];
        ((float4*)tgt_s)[tid] = ((const float4*)(emb + (size_t)iid * DIM))[tid];
    }
    if (tid < DIM) w2_s[tid] = __ldg(aW2 + tid);
    __syncthreads();                                    // sync A

    const int hlen = hist_len[b];

    // ---- S1a: coalesced gather -> bf16 hi/lo tiles, software-pipelined (MLP=4).
    // 13 iterations total; batch 4 LDGs, then convert+store.
    #pragma unroll
    for (int base = 0; base < 16; base += 4) {
        float4 v[4];
        #pragma unroll
        for (int u = 0; u < 4; u++) {
            int it = base + u;
            if (it < 13) {
                int idx = tid + it * NTHREADS;
                int row = idx >> 4;
                int c   = idx & 15;
                v[u] = make_float4(0.f, 0.f, 0.f, 0.f);
                if (row < hlen)
                    v[u] = ((const float4*)(emb + (size_t)hid_s[row] * DIM))[c];
            }
        }
        #pragma unroll
        for (int u = 0; u < 4; u++) {
            int it = base + u;
            if (it < 13) {
                int idx = tid + it * NTHREADS;
                int row = idx >> 4;
                int c   = idx & 15;
                __nv_bfloat162 h01 = __floats2bfloat162_rn(v[u].x, v[u].y);
                __nv_bfloat162 h23 = __floats2bfloat162_rn(v[u].z, v[u].w);
                float lx = v[u].x - __bfloat162float(h01.x);
                float ly = v[u].y - __bfloat162float(h01.y);
                float lz = v[u].z - __bfloat162float(h23.x);
                float lw = v[u].w - __bfloat162float(h23.y);
                __nv_bfloat162 l01 = __floats2bfloat162_rn(lx, ly);
                __nv_bfloat162 l23 = __floats2bfloat162_rn(lz, lw);
                int byteoff = row * 128 + (((c >> 1) ^ (row & 7)) << 4) + (c & 1) * 8;
                uint2 hh = make_uint2(*(unsigned*)&h01, *(unsigned*)&h23);
                uint2 ll = make_uint2(*(unsigned*)&l01, *(unsigned*)&l23);
                *(uint2*)(smc + AHI_OFF + byteoff) = hh;
                *(uint2*)(smc + ALO_OFF + byteoff) = ll;
            }
        }
    }

    // ---- S1b: B tiles (M[d][j] = A1[d][j] + tgt[d]*A3[d][j]) bf16 hi/lo, swizzled.
    {
        int d  = tid >> 2;
        int jq = tid & 3;
        float t = tgt_s[d];
        const float* r1 = aW1 + d * DIM;
        const float* r3 = aW1 + (128 + d) * DIM;
        #pragma unroll
        for (int i = 0; i < 8; i++) {
            int j = jq * 16 + i * 2;
            float m0 = fmaf(t, __ldg(r3 + j),     __ldg(r1 + j));
            float m1 = fmaf(t, __ldg(r3 + j + 1), __ldg(r1 + j + 1));
            __nv_bfloat162 h = __floats2bfloat162_rn(m0, m1);
            float l0f = m0 - __bfloat162float(h.x);
            float l1f = m1 - __bfloat162float(h.y);
            __nv_bfloat162 l = __floats2bfloat162_rn(l0f, l1f);
            int byteoff = d * 128 + ((((jq << 1) + (i >> 2)) ^ (d & 7)) << 4) + (i & 3) * 4;
            *(unsigned*)(smc + BHI_OFF + byteoff) = *(unsigned*)&h;
            *(unsigned*)(smc + BLO_OFF + byteoff) = *(unsigned*)&l;
        }
    }

    // ---- S1c: c_j partials: sum_d tgt[d]*A2[d][j] over 16-d slice
    {
        int jj = tid & 63, g = tid >> 6;
        const float* A2 = aW1 + 64 * DIM;
        float p = 0.f;
        #pragma unroll
        for (int d = g * 16; d < g * 16 + 16; d++)
            p = fmaf(tgt_s[d], __ldg(A2 + d * DIM + jj), p);
        red_s[tid] = p;
    }
    __syncthreads();                                    // sync B

    // ---- S2: finalize c_j; stage relu(c)*w2 for s_pad in red_s[256..319]
    if (tid < DIM) {
        float c = __ldg(ab1 + tid) + red_s[tid] + red_s[64 + tid]
                + red_s[128 + tid] + red_s[192 + tid];
        c_s[tid]         = c;
        red_s[256 + tid] = fmaxf(c, 0.f) * w2_s[tid];
    }
    __syncthreads();                                    // sync C

    // ---- S3a: warp 0 reduces s_pad
    if (wid == 0) {
        float v = red_s[256 + lane] + red_s[288 + lane];
        #pragma unroll
        for (int o = 16; o; o >>= 1) v += __shfl_xor_sync(0xffffffffu, v, o);
        if (lane == 0) spad_s[0] = v;
    }

    // ---- S3b: scores GEMM on tensor pipe (mma.sync bf16, 3-term hi/lo split).
    {
        const int nt = min(13, (hlen + 15) >> 4);
        const int m_off = ((lane >> 3) & 1) * 8 + (lane & 7);
        const int khalf = lane >> 4;
        const int bko   = ((lane >> 3) & 1) * 8 + (lane & 7);

        for (int mt = wid; mt < nt; mt += 8) {
            unsigned aH[4][4], aL[4][4];
            const int r = mt * 16 + m_off;
            #pragma unroll
            for (int k = 0; k < 4; k++) {
                unsigned ad = sbase + AHI_OFF + r * 128 + ((((k << 1) + khalf) ^ (r & 7)) << 4);
                LDSM_X4(aH[k][0], aH[k][1], aH[k][2], aH[k][3], ad);
                LDSM_X4(aL[k][0], aL[k][1], aL[k][2], aL[k][3], ad + (ALO_OFF - AHI_OFF));
            }

            float s0 = 0.f, s1 = 0.f;
            #pragma unroll
            for (int n = 0; n < 8; n++) {
                float d0 = 0.f, d1 = 0.f, d2 = 0.f, d3 = 0.f;
                #pragma unroll
                for (int k = 0; k < 4; k++) {
                    int drow = k * 16 + bko;
                    unsigned bd = sbase + BHI_OFF + drow * 128 + ((n ^ (drow & 7)) << 4);
                    unsigned bh0, bh1, bl0, bl1;
                    LDSM_X2T(bh0, bh1, bd);
                    LDSM_X2T(bl0, bl1, bd + (BLO_OFF - BHI_OFF));
                    MMA_BF16(d0, d1, d2, d3, aH[k][0], aH[k][1], aH[k][2], aH[k][3], bh0, bh1);
                    MMA_BF16(d0, d1, d2, d3, aH[k][0], aH[k][1], aH[k][2], aH[k][3], bl0, bl1);
                    MMA_BF16(d0, d1, d2, d3, aL[k][0], aL[k][1], aL[k][2], aL[k][3], bh0, bh1);
                }
                int j0 = n * 8 + 2 * (lane & 3);
                float c0 = c_s[j0], c1 = c_s[j0 + 1];
                float w0 = w2_s[j0], w1 = w2_s[j0 + 1];
                s0 = fmaf(fmaxf(d0 + c0, 0.f), w0, s0);
                s0 = fmaf(fmaxf(d1 + c1, 0.f), w1, s0);
                s1 = fmaf(fmaxf(d2 + c0, 0.f), w0, s1);
                s1 = fmaf(fmaxf(d3 + c1, 0.f), w1, s1);
            }
            s0 += __shfl_xor_sync(0xffffffffu, s0, 1);
            s0 += __shfl_xor_sync(0xffffffffu, s0, 2);
            s1 += __shfl_xor_sync(0xffffffffu, s1, 1);
            s1 += __shfl_xor_sync(0xffffffffu, s1, 2);
            if ((lane & 3) == 0) {
                int l = mt * 16 + (lane >> 2);
                if (l < HLEN)     sc_s[l]     = s0;
                if (l + 8 < HLEN) sc_s[l + 8] = s1;
            }
        }
    }
    __syncthreads();                                    // sync D

    // ---- S4: fill rows beyond live tiles with s_pad
    {
        float sp = spad_s[0];
        int filled = min(13, (hlen + 15) >> 4) * 16;
        for (int l = filled + tid; l < HLEN; l += NTHREADS) sc_s[l] = sp;
    }
    __syncthreads();                                    // sync E

    // ---- S5: softmax over sc_s[0..199]
    {
        float v = (tid < HLEN) ? sc_s[tid] : -INFINITY;
        float m = v;
        #pragma unroll
        for (int o = 16; o; o >>= 1) m = fmaxf(m, __shfl_xor_sync(0xffffffffu, m, o));
        if (lane == 0) red_s[wid] = m;
        __syncthreads();
        float mm = red_s[0];
        #pragma unroll
        for (int w = 1; w < 8; w++) mm = fmaxf(mm, red_s[w]);

        float e = (tid < HLEN) ? __expf(v - mm) : 0.f;
        float ssum = e;
        #pragma unroll
        for (int o = 16; o; o >>= 1) ssum += __shfl_xor_sync(0xffffffffu, ssum, o);
        if (lane == 0) red_s[8 + wid] = ssum;
        __syncthreads();
        float tot = red_s[8];
        #pragma unroll
        for (int w = 1; w < 8; w++) tot += red_s[8 + w];
        float inv = 1.f / tot;
        if (tid < HLEN) sc_s[tid] = e * inv;
    }
    __syncthreads();

    // ---- S6: pooled[d] = sum_l w[l]*(hi+lo)[l][d]; warp w covers 25 l-rows
    {
        float p0 = 0.f, p1 = 0.f;
        int dp = lane;
        #pragma unroll 5
        for (int i = 0; i < 25; i++) {
            int l = wid * 25 + i;
            float w = sc_s[l];
            int byteoff = l * 128 + (((dp >> 2) ^ (l & 7)) << 4) + (dp & 3) * 4;
            float2 h  = __bfloat1622float2(*(__nv_bfloat162*)(smc + AHI_OFF + byteoff));
            float2 lo = __bfloat1622float2(*(__nv_bfloat162*)(smc + ALO_OFF + byteoff));
            p0 = fmaf(w, h.x + lo.x, p0);
            p1 = fmaf(w, h.y + lo.y, p1);
        }
        red_s[wid * 64 + 2 * dp]     = p0;
        red_s[wid * 64 + 2 * dp + 1] = p1;
    }
    __syncthreads();

    // ---- S7: write comb = [tgt, pooled, pooled - tgt] to global scratch
    if (tid < DIM) {
        float pooled = 0.f;
        #pragma unroll
        for (int w = 0; w < 8; w++) pooled += red_s[w * 64 + tid];
        float tg = tgt_s[tid];
        float* gc = g_comb + (size_t)b * 192;
        gc[tid]        = tg;
        gc[64 + tid]   = pooled;
        gc[128 + tid]  = pooled - tg;
    }
}

// ============================ kernel 2: batched MLP ==========================
#define K2_ROWS 32

__global__ __launch_bounds__(256)
void mlp_kernel(const float* __restrict__ fW1, const float* __restrict__ fb1,
                const float* __restrict__ fW2, const float* __restrict__ fb2,
                const float* __restrict__ fW3, const float* __restrict__ fb3,
                float* __restrict__ out, int nb)
{
    __shared__ float comb_s[K2_ROWS * 192];   // 24576 B
    __shared__ float z1_s[K2_ROWS * 128];     // 16384 B
    __shared__ float z2_s[K2_ROWS * 64];      //  8192 B

    const int tid = threadIdx.x;
    const int r0  = blockIdx.x * K2_ROWS;

    // load comb rows (zero rows past nb)
    {
        const float4* src = (const float4*)(g_comb + (size_t)r0 * 192);
        for (int i = tid; i < K2_ROWS * 48; i += 256) {
            float4 v = make_float4(0.f, 0.f, 0.f, 0.f);
            if (r0 + i / 48 < nb) v = src[i];
            ((float4*)comb_s)[i] = v;
        }
    }
    __syncthreads();

    // layer 1: z1[r][j] = relu(comb[r] . fW1[:,j] + fb1[j]); thread = (j, rowhalf)
    {
        int j = tid & 127;
        int h = tid >> 7;              // rows 16h .. 16h+15
        float acc[16];
        float bias = __ldg(fb1 + j);
        #pragma unroll
        for (int rr = 0; rr < 16; rr++) acc[rr] = bias;
        for (int k4 = 0; k4 < 48; k4++) {
            int k = k4 * 4;
            float w0 = __ldg(fW1 + (k + 0) * 128 + j);
            float w1 = __ldg(fW1 + (k + 1) * 128 + j);
            float w2 = __ldg(fW1 + (k + 2) * 128 + j);
            float w3 = __ldg(fW1 + (k + 3) * 128 + j);
            #pragma unroll
            for (int rr = 0; rr < 16; rr++) {
                float4 c = *(const float4*)(comb_s + (h * 16 + rr) * 192 + k);
                float a = acc[rr];
                a = fmaf(c.x, w0, a);
                a = fmaf(c.y, w1, a);
                a = fmaf(c.z, w2, a);
                a = fmaf(c.w, w3, a);
                acc[rr] = a;
            }
        }
        #pragma unroll
        for (int rr = 0; rr < 16; rr++)
            z1_s[(h * 16 + rr) * 128 + j] = fmaxf(acc[rr], 0.f);
    }
    __syncthreads();

    // layer 2: z2[r][j] = relu(z1[r] . fW2[:,j] + fb2[j]); thread = (j, quarter)
    {
        int j = tid & 63;
        int q = tid >> 6;              // rows 8q .. 8q+7
        float acc[8];
        float bias = __ldg(fb2 + j);
        #pragma unroll
        for (int rr = 0; rr < 8; rr++) acc[rr] = bias;
        for (int k4 = 0; k4 < 32; k4++) {
            int k = k4 * 4;
            float w0 = __ldg(fW2 + (k + 0) * 64 + j);
            float w1 = __ldg(fW2 + (k + 1) * 64 + j);
            float w2 = __ldg(fW2 + (k + 2) * 64 + j);
            float w3 = __ldg(fW2 + (k + 3) * 64 + j);
            #pragma unroll
            for (int rr = 0; rr < 8; rr++) {
                float4 c = *(const float4*)(z1_s + (q * 8 + rr) * 128 + k);
                float a = acc[rr];
                a = fmaf(c.x, w0, a);
                a = fmaf(c.y, w1, a);
                a = fmaf(c.z, w2, a);
                a = fmaf(c.w, w3, a);
                acc[rr] = a;
            }
        }
        #pragma unroll
        for (int rr = 0; rr < 8; rr++)
            z2_s[(q * 8 + rr) * 64 + j] = fmaxf(acc[rr], 0.f);
    }
    __syncthreads();

    // layer 3: out[r] = sigmoid(z2[r] . fW3 + fb3)
    if (tid < K2_ROWS) {
        float a0 = 0.f, a1 = 0.f, a2 = 0.f, a3 = 0.f;
        const float* zr = z2_s + tid * 64;
        #pragma unroll 4
        for (int k = 0; k < 64; k += 4) {
            a0 = fmaf(zr[k + 0], __ldg(fW3 + k + 0), a0);
            a1 = fmaf(zr[k + 1], __ldg(fW3 + k + 1), a1);
            a2 = fmaf(zr[k + 2], __ldg(fW3 + k + 2), a2);
            a3 = fmaf(zr[k + 3], __ldg(fW3 + k + 3), a3);
        }
        float z = (a0 + a1) + (a2 + a3) + __ldg(fb3);
        if (r0 + tid < nb)
            out[r0 + tid] = 1.f / (1.f + __expf(-z));
    }
}

extern "C" void kernel_launch(void* const* d_in, const int* in_sizes, int n_in,
                              void* d_out, int out_size)
{
    const int*   item_ids = (const int*)  d_in[0];
    const int*   history  = (const int*)  d_in[1];
    const int*   hist_len = (const int*)  d_in[2];
    const float* emb      = (const float*)d_in[3];
    const float* aW1      = (const float*)d_in[4];
    const float* ab1      = (const float*)d_in[5];
    const float* aW2      = (const float*)d_in[6];
    // d_in[7] = ab2 — dropped (softmax shift-invariant)
    const float* fW1      = (const float*)d_in[8];
    const float* fb1      = (const float*)d_in[9];
    const float* fW2      = (const float*)d_in[10];
    const float* fb2      = (const float*)d_in[11];
    const float* fW3      = (const float*)d_in[12];
    const float* fb3      = (const float*)d_in[13];
    float* out = (float*)d_out;

    const int nb = in_sizes[0];

    cudaFuncSetAttribute(din_kernel, cudaFuncAttributeMaxDynamicSharedMemorySize, SMEM_BYTES);
    din_kernel<<<nb, NTHREADS, SMEM_BYTES>>>(
        item_ids, history, hist_len, emb, aW1, ab1, aW2);
    mlp_kernel<<<(nb + K2_ROWS - 1) / K2_ROWS, 256>>>(
        fW1, fb1, fW2, fb2, fW3, fb3, out, nb);
}

// round 9
// speedup vs baseline: 1.5651x; 1.0222x over previous
#include <cuda_runtime.h>
#include <cuda_bf16.h>
#include <math.h>

#define NTHREADS 256
#define HLEN     200
#define AROWS    208           // 13 m16-tiles
#define DIM      64
#define MAXB     4096

// ---- K1 dynamic smem layout (bytes) ----
// bf16 tiles: 128B rows, chunk-XOR swizzle: byte(row,chunk)=row*128+((chunk^(row&7))<<4)
#define AHI_OFF   0                      // hist hi: 208 x 64 bf16 = 26624 B
#define ALO_OFF   26624                  // hist lo: 26624 B
#define BHI_OFF   53248                  // M hi: 64 x 64 bf16 = 8192 B
#define BLO_OFF   61440                  // M lo: 8192 B
#define FBASE     69632                  // fp32 region (floats below)
#define F_TGT   (FBASE/4 + 0)            // 64
#define F_C     (F_TGT + 64)             // 64
#define F_W2    (F_C + 64)               // 64
#define F_SC    (F_W2 + 64)              // 200
#define F_RED   (F_SC + 200)             // 512
#define F_HID   (F_RED + 512)            // 200 (int)
#define F_SPAD  (F_HID + 200)            // 1
#define SMEM_FLOATS (F_SPAD + 1)
#define SMEM_BYTES  (SMEM_FLOATS * 4)

// inter-kernel scratch: comb = [tgt, pooled, pooled - tgt] per batch row
__device__ float g_comb[MAXB * 192];

__device__ __forceinline__ unsigned smem_u32(const void* p) {
    unsigned a;
    asm("{ .reg .u64 t; cvta.to.shared.u64 t, %1; cvt.u32.u64 %0, t; }"
        : "=r"(a) : "l"(p));
    return a;
}

#define LDSM_X4(r0, r1, r2, r3, addr) \
    asm volatile("ldmatrix.sync.aligned.m8n8.x4.shared.b16 {%0,%1,%2,%3}, [%4];" \
        : "=r"(r0), "=r"(r1), "=r"(r2), "=r"(r3) : "r"(addr))

#define LDSM_X2T(r0, r1, addr) \
    asm volatile("ldmatrix.sync.aligned.m8n8.x2.trans.shared.b16 {%0,%1}, [%2];" \
        : "=r"(r0), "=r"(r1) : "r"(addr))

#define MMA_BF16(d0, d1, d2, d3, a0, a1, a2, a3, b0, b1) \
    asm volatile("mma.sync.aligned.m16n8k16.row.col.f32.bf16.bf16.f32 " \
        "{%0,%1,%2,%3}, {%4,%5,%6,%7}, {%8,%9}, {%0,%1,%2,%3};" \
        : "+f"(d0), "+f"(d1), "+f"(d2), "+f"(d3) \
        : "r"(a0), "r"(a1), "r"(a2), "r"(a3), "r"(b0), "r"(b1))

__global__ __launch_bounds__(NTHREADS, 3)
void din_kernel(const int*   __restrict__ item_ids,
                const int*   __restrict__ history,
                const int*   __restrict__ hist_len,
                const float* __restrict__ emb,
                const float* __restrict__ aW1,
                const float* __restrict__ ab1,
                const float* __restrict__ aW2)
{
    extern __shared__ float sm[];
    char*  smc    = (char*)sm;
    float* tgt_s  = sm + F_TGT;
    float* c_s    = sm + F_C;
    float* w2_s   = sm + F_W2;
    float* sc_s   = sm + F_SC;
    float* red_s  = sm + F_RED;
    int*   hid_s  = (int*)(sm + F_HID);
    float* spad_s = sm + F_SPAD;

    const int b    = blockIdx.x;
    const int tid  = threadIdx.x;
    const int lane = tid & 31;
    const int wid  = tid >> 5;
    const unsigned sbase = smem_u32(sm);

    // ---- S0: history ids + target embedding + w2
    if (tid < HLEN) hid_s[tid] = history[b * HLEN + tid];
    if (tid < 16) {
        int iid = item_ids[b];
        ((float4*)tgt_s)[tid] = ((const float4*)(emb + (size_t)iid * DIM))[tid];
    }
    if (tid < DIM) w2_s[tid] = __ldg(aW2 + tid);
    __syncthreads();                                    // sync A

    const int hlen = hist_len[b];

    // ---- S1a: coalesced gather -> bf16 hi/lo tiles, software-pipelined (MLP=4).
    #pragma unroll
    for (int base = 0; base < 16; base += 4) {
        float4 v[4];
        #pragma unroll
        for (int u = 0; u < 4; u++) {
            int it = base + u;
            if (it < 13) {
                int idx = tid + it * NTHREADS;
                int row = idx >> 4;
                int c   = idx & 15;
                v[u] = make_float4(0.f, 0.f, 0.f, 0.f);
                if (row < hlen)
                    v[u] = ((const float4*)(emb + (size_t)hid_s[row] * DIM))[c];
            }
        }
        #pragma unroll
        for (int u = 0; u < 4; u++) {
            int it = base + u;
            if (it < 13) {
                int idx = tid + it * NTHREADS;
                int row = idx >> 4;
                int c   = idx & 15;
                __nv_bfloat162 h01 = __floats2bfloat162_rn(v[u].x, v[u].y);
                __nv_bfloat162 h23 = __floats2bfloat162_rn(v[u].z, v[u].w);
                float lx = v[u].x - __bfloat162float(h01.x);
                float ly = v[u].y - __bfloat162float(h01.y);
                float lz = v[u].z - __bfloat162float(h23.x);
                float lw = v[u].w - __bfloat162float(h23.y);
                __nv_bfloat162 l01 = __floats2bfloat162_rn(lx, ly);
                __nv_bfloat162 l23 = __floats2bfloat162_rn(lz, lw);
                int byteoff = row * 128 + (((c >> 1) ^ (row & 7)) << 4) + (c & 1) * 8;
                uint2 hh = make_uint2(*(unsigned*)&h01, *(unsigned*)&h23);
                uint2 ll = make_uint2(*(unsigned*)&l01, *(unsigned*)&l23);
                *(uint2*)(smc + AHI_OFF + byteoff) = hh;
                *(uint2*)(smc + ALO_OFF + byteoff) = ll;
            }
        }
    }

    // ---- S1b: B tiles (M[d][j] = A1[d][j] + tgt[d]*A3[d][j]) bf16 hi/lo, swizzled.
    {
        int d  = tid >> 2;
        int jq = tid & 3;
        float t = tgt_s[d];
        const float* r1 = aW1 + d * DIM;
        const float* r3 = aW1 + (128 + d) * DIM;
        #pragma unroll
        for (int i = 0; i < 8; i++) {
            int j = jq * 16 + i * 2;
            float m0 = fmaf(t, __ldg(r3 + j),     __ldg(r1 + j));
            float m1 = fmaf(t, __ldg(r3 + j + 1), __ldg(r1 + j + 1));
            __nv_bfloat162 h = __floats2bfloat162_rn(m0, m1);
            float l0f = m0 - __bfloat162float(h.x);
            float l1f = m1 - __bfloat162float(h.y);
            __nv_bfloat162 l = __floats2bfloat162_rn(l0f, l1f);
            int byteoff = d * 128 + ((((jq << 1) + (i >> 2)) ^ (d & 7)) << 4) + (i & 3) * 4;
            *(unsigned*)(smc + BHI_OFF + byteoff) = *(unsigned*)&h;
            *(unsigned*)(smc + BLO_OFF + byteoff) = *(unsigned*)&l;
        }
    }

    // ---- S1c: c_j partials: sum_d tgt[d]*A2[d][j] over 16-d slice
    {
        int jj = tid & 63, g = tid >> 6;
        const float* A2 = aW1 + 64 * DIM;
        float p = 0.f;
        #pragma unroll
        for (int d = g * 16; d < g * 16 + 16; d++)
            p = fmaf(tgt_s[d], __ldg(A2 + d * DIM + jj), p);
        red_s[tid] = p;
    }
    __syncthreads();                                    // sync B

    // ---- S2: finalize c_j; stage relu(c)*w2 for s_pad in red_s[256..319]
    if (tid < DIM) {
        float c = __ldg(ab1 + tid) + red_s[tid] + red_s[64 + tid]
                + red_s[128 + tid] + red_s[192 + tid];
        c_s[tid]         = c;
        red_s[256 + tid] = fmaxf(c, 0.f) * w2_s[tid];
    }
    __syncthreads();                                    // sync C

    // ---- S3a: warp 0 reduces s_pad
    if (wid == 0) {
        float v = red_s[256 + lane] + red_s[288 + lane];
        #pragma unroll
        for (int o = 16; o; o >>= 1) v += __shfl_xor_sync(0xffffffffu, v, o);
        if (lane == 0) spad_s[0] = v;
    }

    // ---- S3b: scores GEMM on tensor pipe (mma.sync bf16, 3-term hi/lo split).
    {
        const int nt = min(13, (hlen + 15) >> 4);
        const int m_off = ((lane >> 3) & 1) * 8 + (lane & 7);
        const int khalf = lane >> 4;
        const int bko   = ((lane >> 3) & 1) * 8 + (lane & 7);

        for (int mt = wid; mt < nt; mt += 8) {
            unsigned aH[4][4], aL[4][4];
            const int r = mt * 16 + m_off;
            #pragma unroll
            for (int k = 0; k < 4; k++) {
                unsigned ad = sbase + AHI_OFF + r * 128 + ((((k << 1) + khalf) ^ (r & 7)) << 4);
                LDSM_X4(aH[k][0], aH[k][1], aH[k][2], aH[k][3], ad);
                LDSM_X4(aL[k][0], aL[k][1], aL[k][2], aL[k][3], ad + (ALO_OFF - AHI_OFF));
            }

            float s0 = 0.f, s1 = 0.f;
            #pragma unroll
            for (int n = 0; n < 8; n++) {
                float d0 = 0.f, d1 = 0.f, d2 = 0.f, d3 = 0.f;
                #pragma unroll
                for (int k = 0; k < 4; k++) {
                    int drow = k * 16 + bko;
                    unsigned bd = sbase + BHI_OFF + drow * 128 + ((n ^ (drow & 7)) << 4);
                    unsigned bh0, bh1, bl0, bl1;
                    LDSM_X2T(bh0, bh1, bd);
                    LDSM_X2T(bl0, bl1, bd + (BLO_OFF - BHI_OFF));
                    MMA_BF16(d0, d1, d2, d3, aH[k][0], aH[k][1], aH[k][2], aH[k][3], bh0, bh1);
                    MMA_BF16(d0, d1, d2, d3, aH[k][0], aH[k][1], aH[k][2], aH[k][3], bl0, bl1);
                    MMA_BF16(d0, d1, d2, d3, aL[k][0], aL[k][1], aL[k][2], aL[k][3], bh0, bh1);
                }
                int j0 = n * 8 + 2 * (lane & 3);
                float c0 = c_s[j0], c1 = c_s[j0 + 1];
                float w0 = w2_s[j0], w1 = w2_s[j0 + 1];
                s0 = fmaf(fmaxf(d0 + c0, 0.f), w0, s0);
                s0 = fmaf(fmaxf(d1 + c1, 0.f), w1, s0);
                s1 = fmaf(fmaxf(d2 + c0, 0.f), w0, s1);
                s1 = fmaf(fmaxf(d3 + c1, 0.f), w1, s1);
            }
            s0 += __shfl_xor_sync(0xffffffffu, s0, 1);
            s0 += __shfl_xor_sync(0xffffffffu, s0, 2);
            s1 += __shfl_xor_sync(0xffffffffu, s1, 1);
            s1 += __shfl_xor_sync(0xffffffffu, s1, 2);
            if ((lane & 3) == 0) {
                int l = mt * 16 + (lane >> 2);
                if (l < HLEN)     sc_s[l]     = s0;
                if (l + 8 < HLEN) sc_s[l + 8] = s1;
            }
        }
    }
    __syncthreads();                                    // sync D

    // ---- S4: fill rows beyond live tiles with s_pad
    {
        float sp = spad_s[0];
        int filled = min(13, (hlen + 15) >> 4) * 16;
        for (int l = filled + tid; l < HLEN; l += NTHREADS) sc_s[l] = sp;
    }
    __syncthreads();                                    // sync E

    // ---- S5: softmax over sc_s[0..199]
    {
        float v = (tid < HLEN) ? sc_s[tid] : -INFINITY;
        float m = v;
        #pragma unroll
        for (int o = 16; o; o >>= 1) m = fmaxf(m, __shfl_xor_sync(0xffffffffu, m, o));
        if (lane == 0) red_s[wid] = m;
        __syncthreads();
        float mm = red_s[0];
        #pragma unroll
        for (int w = 1; w < 8; w++) mm = fmaxf(mm, red_s[w]);

        float e = (tid < HLEN) ? __expf(v - mm) : 0.f;
        float ssum = e;
        #pragma unroll
        for (int o = 16; o; o >>= 1) ssum += __shfl_xor_sync(0xffffffffu, ssum, o);
        if (lane == 0) red_s[8 + wid] = ssum;
        __syncthreads();
        float tot = red_s[8];
        #pragma unroll
        for (int w = 1; w < 8; w++) tot += red_s[8 + w];
        float inv = 1.f / tot;
        if (tid < HLEN) sc_s[tid] = e * inv;
    }
    __syncthreads();

    // ---- S6: pooled[d] = sum_l w[l]*(hi+lo)[l][d]; warp w covers 25 l-rows
    {
        float p0 = 0.f, p1 = 0.f;
        int dp = lane;
        #pragma unroll 5
        for (int i = 0; i < 25; i++) {
            int l = wid * 25 + i;
            float w = sc_s[l];
            int byteoff = l * 128 + (((dp >> 2) ^ (l & 7)) << 4) + (dp & 3) * 4;
            float2 h  = __bfloat1622float2(*(__nv_bfloat162*)(smc + AHI_OFF + byteoff));
            float2 lo = __bfloat1622float2(*(__nv_bfloat162*)(smc + ALO_OFF + byteoff));
            p0 = fmaf(w, h.x + lo.x, p0);
            p1 = fmaf(w, h.y + lo.y, p1);
        }
        red_s[wid * 64 + 2 * dp]     = p0;
        red_s[wid * 64 + 2 * dp + 1] = p1;
    }
    __syncthreads();

    // ---- S7: write comb = [tgt, pooled, pooled - tgt] to global scratch
    if (tid < DIM) {
        float pooled = 0.f;
        #pragma unroll
        for (int w = 0; w < 8; w++) pooled += red_s[w * 64 + tid];
        float tg = tgt_s[tid];
        float* gc = g_comb + (size_t)b * 192;
        gc[tid]        = tg;
        gc[64 + tid]   = pooled;
        gc[128 + tid]  = pooled - tg;
    }
}

// ============================ kernel 2: batched MLP ==========================
// 8 rows per CTA -> 512 CTAs (3.5/SM): occupancy-driven, weights stay L2-hot.
#define K2_ROWS 8

__global__ __launch_bounds__(256)
void mlp_kernel(const float* __restrict__ fW1, const float* __restrict__ fb1,
                const float* __restrict__ fW2, const float* __restrict__ fb2,
                const float* __restrict__ fW3, const float* __restrict__ fb3,
                float* __restrict__ out, int nb)
{
    __shared__ float comb_s[K2_ROWS * 192];   // 6144 B
    __shared__ float z1_s[K2_ROWS * 128];     // 4096 B
    __shared__ float z2_s[K2_ROWS * 64];      // 2048 B

    const int tid = threadIdx.x;
    const int r0  = blockIdx.x * K2_ROWS;

    // load comb rows (zero rows past nb)
    {
        const float4* src = (const float4*)(g_comb + (size_t)r0 * 192);
        for (int i = tid; i < K2_ROWS * 48; i += 256) {
            float4 v = make_float4(0.f, 0.f, 0.f, 0.f);
            if (r0 + i / 48 < nb) v = src[i];
            ((float4*)comb_s)[i] = v;
        }
    }
    __syncthreads();

    // layer 1: z1[r][j] = relu(comb[r] . fW1[:,j] + fb1[j]); thread = (j, rowhalf)
    {
        int j = tid & 127;
        int h = tid >> 7;              // rows 4h .. 4h+3
        float acc[4];
        float bias = __ldg(fb1 + j);
        #pragma unroll
        for (int rr = 0; rr < 4; rr++) acc[rr] = bias;
        #pragma unroll 4
        for (int k4 = 0; k4 < 48; k4++) {
            int k = k4 * 4;
            float w0 = __ldg(fW1 + (k + 0) * 128 + j);
            float w1 = __ldg(fW1 + (k + 1) * 128 + j);
            float w2 = __ldg(fW1 + (k + 2) * 128 + j);
            float w3 = __ldg(fW1 + (k + 3) * 128 + j);
            #pragma unroll
            for (int rr = 0; rr < 4; rr++) {
                float4 c = *(const float4*)(comb_s + (h * 4 + rr) * 192 + k);
                float a = acc[rr];
                a = fmaf(c.x, w0, a);
                a = fmaf(c.y, w1, a);
                a = fmaf(c.z, w2, a);
                a = fmaf(c.w, w3, a);
                acc[rr] = a;
            }
        }
        #pragma unroll
        for (int rr = 0; rr < 4; rr++)
            z1_s[(h * 4 + rr) * 128 + j] = fmaxf(acc[rr], 0.f);
    }
    __syncthreads();

    // layer 2: z2[r][j] = relu(z1[r] . fW2[:,j] + fb2[j]); thread = (j, quarter)
    {
        int j = tid & 63;
        int q = tid >> 6;              // rows 2q, 2q+1
        float acc[2];
        float bias = __ldg(fb2 + j);
        acc[0] = bias; acc[1] = bias;
        #pragma unroll 4
        for (int k4 = 0; k4 < 32; k4++) {
            int k = k4 * 4;
            float w0 = __ldg(fW2 + (k + 0) * 64 + j);
            float w1 = __ldg(fW2 + (k + 1) * 64 + j);
            float w2 = __ldg(fW2 + (k + 2) * 64 + j);
            float w3 = __ldg(fW2 + (k + 3) * 64 + j);
            #pragma unroll
            for (int rr = 0; rr < 2; rr++) {
                float4 c = *(const float4*)(z1_s + (q * 2 + rr) * 128 + k);
                float a = acc[rr];
                a = fmaf(c.x, w0, a);
                a = fmaf(c.y, w1, a);
                a = fmaf(c.z, w2, a);
                a = fmaf(c.w, w3, a);
                acc[rr] = a;
            }
        }
        #pragma unroll
        for (int rr = 0; rr < 2; rr++)
            z2_s[(q * 2 + rr) * 64 + j] = fmaxf(acc[rr], 0.f);
    }
    __syncthreads();

    // layer 3: warp per row; lanes split the 64-long dot, shuffle-reduce
    {
        int w    = tid >> 5;          // row 0..7
        int lane = tid & 31;
        const float* zr = z2_s + w * 64;
        float a = fmaf(zr[lane], __ldg(fW3 + lane),
                       zr[lane + 32] * __ldg(fW3 + lane + 32));
        #pragma unroll
        for (int o = 16; o; o >>= 1) a += __shfl_xor_sync(0xffffffffu, a, o);
        if (lane == 0 && r0 + w < nb) {
            float z = a + __ldg(fb3);
            out[r0 + w] = 1.f / (1.f + __expf(-z));
        }
    }
}

extern "C" void kernel_launch(void* const* d_in, const int* in_sizes, int n_in,
                              void* d_out, int out_size)
{
    const int*   item_ids = (const int*)  d_in[0];
    const int*   history  = (const int*)  d_in[1];
    const int*   hist_len = (const int*)  d_in[2];
    const float* emb      = (const float*)d_in[3];
    const float* aW1      = (const float*)d_in[4];
    const float* ab1      = (const float*)d_in[5];
    const float* aW2      = (const float*)d_in[6];
    // d_in[7] = ab2 — dropped (softmax shift-invariant)
    const float* fW1      = (const float*)d_in[8];
    const float* fb1      = (const float*)d_in[9];
    const float* fW2      = (const float*)d_in[10];
    const float* fb2      = (const float*)d_in[11];
    const float* fW3      = (const float*)d_in[12];
    const float* fb3      = (const float*)d_in[13];
    float* out = (float*)d_out;

    const int nb = in_sizes[0];

    cudaFuncSetAttribute(din_kernel, cudaFuncAttributeMaxDynamicSharedMemorySize, SMEM_BYTES);
    din_kernel<<<nb, NTHREADS, SMEM_BYTES>>>(
        item_ids, history, hist_len, emb, aW1, ab1, aW2);
    mlp_kernel<<<(nb + K2_ROWS - 1) / K2_ROWS, 256>>>(
        fW1, fb1, fW2, fb2, fW3, fb3, out, nb);
}

// round 10
// speedup vs baseline: 1.5909x; 1.0165x over previous
#include <cuda_runtime.h>
#include <cuda_bf16.h>
#include <math.h>

#define NTHREADS 256
#define HLEN     200
#define AROWS    208           // 13 m16-tiles
#define DIM      64
#define MAXB     4096

// ---- K1 dynamic smem layout (bytes) ----
// bf16 tiles: 128B rows, chunk-XOR swizzle: byte(row,chunk)=row*128+((chunk^(row&7))<<4)
#define AHI_OFF   0                      // hist hi: 208 x 64 bf16 = 26624 B
#define ALO_OFF   26624                  // hist lo: 26624 B
#define BHI_OFF   53248                  // M hi: 64 x 64 bf16 = 8192 B
#define BLO_OFF   61440                  // M lo: 8192 B
#define FBASE     69632                  // fp32 region (floats below)
#define F_TGT   (FBASE/4 + 0)            // 64
#define F_C     (F_TGT + 64)             // 64
#define F_W2    (F_C + 64)               // 64
#define F_SC    (F_W2 + 64)              // 200
#define F_RED   (F_SC + 200)             // 512
#define F_HID   (F_RED + 512)            // 200 (int)
#define F_SPAD  (F_HID + 200)            // 1
#define SMEM_FLOATS (F_SPAD + 1)
#define SMEM_BYTES  (SMEM_FLOATS * 4)

// inter-kernel scratch: comb = [tgt, pooled, pooled - tgt] per batch row
__device__ float g_comb[MAXB * 192];

__device__ __forceinline__ unsigned smem_u32(const void* p) {
    unsigned a;
    asm("{ .reg .u64 t; cvta.to.shared.u64 t, %1; cvt.u32.u64 %0, t; }"
        : "=r"(a) : "l"(p));
    return a;
}

#define LDSM_X4(r0, r1, r2, r3, addr) \
    asm volatile("ldmatrix.sync.aligned.m8n8.x4.shared.b16 {%0,%1,%2,%3}, [%4];" \
        : "=r"(r0), "=r"(r1), "=r"(r2), "=r"(r3) : "r"(addr))

#define LDSM_X2T(r0, r1, addr) \
    asm volatile("ldmatrix.sync.aligned.m8n8.x2.trans.shared.b16 {%0,%1}, [%2];" \
        : "=r"(r0), "=r"(r1) : "r"(addr))

#define MMA_BF16(d0, d1, d2, d3, a0, a1, a2, a3, b0, b1) \
    asm volatile("mma.sync.aligned.m16n8k16.row.col.f32.bf16.bf16.f32 " \
        "{%0,%1,%2,%3}, {%4,%5,%6,%7}, {%8,%9}, {%0,%1,%2,%3};" \
        : "+f"(d0), "+f"(d1), "+f"(d2), "+f"(d3) \
        : "r"(a0), "r"(a1), "r"(a2), "r"(a3), "r"(b0), "r"(b1))

__global__ __launch_bounds__(NTHREADS, 3)
void din_kernel(const int*   __restrict__ item_ids,
                const int*   __restrict__ history,
                const int*   __restrict__ hist_len,
                const float* __restrict__ emb,
                const float* __restrict__ aW1,
                const float* __restrict__ ab1,
                const float* __restrict__ aW2)
{
    extern __shared__ float sm[];
    char*  smc    = (char*)sm;
    float* tgt_s  = sm + F_TGT;
    float* c_s    = sm + F_C;
    float* w2_s   = sm + F_W2;
    float* sc_s   = sm + F_SC;
    float* red_s  = sm + F_RED;
    int*   hid_s  = (int*)(sm + F_HID);
    float* spad_s = sm + F_SPAD;

    const int b    = blockIdx.x;
    const int tid  = threadIdx.x;
    const int lane = tid & 31;
    const int wid  = tid >> 5;
    const unsigned sbase = smem_u32(sm);

    // ---- S0: history ids + target embedding + w2
    if (tid < HLEN) hid_s[tid] = history[b * HLEN + tid];
    if (tid < 16) {
        int iid = item_ids[b];
        ((float4*)tgt_s)[tid] = ((const float4*)(emb + (size_t)iid * DIM))[tid];
    }
    if (tid < DIM) w2_s[tid] = __ldg(aW2 + tid);
    __syncthreads();                                    // sync A

    const int hlen = hist_len[b];

    // ---- S1a: coalesced gather -> bf16 hi/lo tiles, software-pipelined (MLP=4).
    #pragma unroll
    for (int base = 0; base < 16; base += 4) {
        float4 v[4];
        #pragma unroll
        for (int u = 0; u < 4; u++) {
            int it = base + u;
            if (it < 13) {
                int idx = tid + it * NTHREADS;
                int row = idx >> 4;
                int c   = idx & 15;
                v[u] = make_float4(0.f, 0.f, 0.f, 0.f);
                if (row < hlen)
                    v[u] = ((const float4*)(emb + (size_t)hid_s[row] * DIM))[c];
            }
        }
        #pragma unroll
        for (int u = 0; u < 4; u++) {
            int it = base + u;
            if (it < 13) {
                int idx = tid + it * NTHREADS;
                int row = idx >> 4;
                int c   = idx & 15;
                __nv_bfloat162 h01 = __floats2bfloat162_rn(v[u].x, v[u].y);
                __nv_bfloat162 h23 = __floats2bfloat162_rn(v[u].z, v[u].w);
                float lx = v[u].x - __bfloat162float(h01.x);
                float ly = v[u].y - __bfloat162float(h01.y);
                float lz = v[u].z - __bfloat162float(h23.x);
                float lw = v[u].w - __bfloat162float(h23.y);
                __nv_bfloat162 l01 = __floats2bfloat162_rn(lx, ly);
                __nv_bfloat162 l23 = __floats2bfloat162_rn(lz, lw);
                int byteoff = row * 128 + (((c >> 1) ^ (row & 7)) << 4) + (c & 1) * 8;
                uint2 hh = make_uint2(*(unsigned*)&h01, *(unsigned*)&h23);
                uint2 ll = make_uint2(*(unsigned*)&l01, *(unsigned*)&l23);
                *(uint2*)(smc + AHI_OFF + byteoff) = hh;
                *(uint2*)(smc + ALO_OFF + byteoff) = ll;
            }
        }
    }

    // ---- S1b: B tiles (M[d][j] = A1[d][j] + tgt[d]*A3[d][j]) bf16 hi/lo, swizzled.
    {
        int d  = tid >> 2;
        int jq = tid & 3;
        float t = tgt_s[d];
        const float* r1 = aW1 + d * DIM;
        const float* r3 = aW1 + (128 + d) * DIM;
        #pragma unroll
        for (int i = 0; i < 8; i++) {
            int j = jq * 16 + i * 2;
            float m0 = fmaf(t, __ldg(r3 + j),     __ldg(r1 + j));
            float m1 = fmaf(t, __ldg(r3 + j + 1), __ldg(r1 + j + 1));
            __nv_bfloat162 h = __floats2bfloat162_rn(m0, m1);
            float l0f = m0 - __bfloat162float(h.x);
            float l1f = m1 - __bfloat162float(h.y);
            __nv_bfloat162 l = __floats2bfloat162_rn(l0f, l1f);
            int byteoff = d * 128 + ((((jq << 1) + (i >> 2)) ^ (d & 7)) << 4) + (i & 3) * 4;
            *(unsigned*)(smc + BHI_OFF + byteoff) = *(unsigned*)&h;
            *(unsigned*)(smc + BLO_OFF + byteoff) = *(unsigned*)&l;
        }
    }

    // ---- S1c: c_j partials: sum_d tgt[d]*A2[d][j] over 16-d slice
    {
        int jj = tid & 63, g = tid >> 6;
        const float* A2 = aW1 + 64 * DIM;
        float p = 0.f;
        #pragma unroll
        for (int d = g * 16; d < g * 16 + 16; d++)
            p = fmaf(tgt_s[d], __ldg(A2 + d * DIM + jj), p);
        red_s[tid] = p;
    }
    __syncthreads();                                    // sync B

    // ---- S2: finalize c_j; stage relu(c)*w2 for s_pad in red_s[256..319]
    if (tid < DIM) {
        float c = __ldg(ab1 + tid) + red_s[tid] + red_s[64 + tid]
                + red_s[128 + tid] + red_s[192 + tid];
        c_s[tid]         = c;
        red_s[256 + tid] = fmaxf(c, 0.f) * w2_s[tid];
    }
    __syncthreads();                                    // sync C

    // ---- S3a: warp 0 reduces s_pad
    if (wid == 0) {
        float v = red_s[256 + lane] + red_s[288 + lane];
        #pragma unroll
        for (int o = 16; o; o >>= 1) v += __shfl_xor_sync(0xffffffffu, v, o);
        if (lane == 0) spad_s[0] = v;
    }

    // ---- S3b: scores GEMM on tensor pipe (mma.sync bf16, 3-term hi/lo split).
    {
        const int nt = min(13, (hlen + 15) >> 4);
        const int m_off = ((lane >> 3) & 1) * 8 + (lane & 7);
        const int khalf = lane >> 4;
        const int bko   = ((lane >> 3) & 1) * 8 + (lane & 7);

        for (int mt = wid; mt < nt; mt += 8) {
            unsigned aH[4][4], aL[4][4];
            const int r = mt * 16 + m_off;
            #pragma unroll
            for (int k = 0; k < 4; k++) {
                unsigned ad = sbase + AHI_OFF + r * 128 + ((((k << 1) + khalf) ^ (r & 7)) << 4);
                LDSM_X4(aH[k][0], aH[k][1], aH[k][2], aH[k][3], ad);
                LDSM_X4(aL[k][0], aL[k][1], aL[k][2], aL[k][3], ad + (ALO_OFF - AHI_OFF));
            }

            float s0 = 0.f, s1 = 0.f;
            #pragma unroll
            for (int n = 0; n < 8; n++) {
                float d0 = 0.f, d1 = 0.f, d2 = 0.f, d3 = 0.f;
                #pragma unroll
                for (int k = 0; k < 4; k++) {
                    int drow = k * 16 + bko;
                    unsigned bd = sbase + BHI_OFF + drow * 128 + ((n ^ (drow & 7)) << 4);
                    unsigned bh0, bh1, bl0, bl1;
                    LDSM_X2T(bh0, bh1, bd);
                    LDSM_X2T(bl0, bl1, bd + (BLO_OFF - BHI_OFF));
                    MMA_BF16(d0, d1, d2, d3, aH[k][0], aH[k][1], aH[k][2], aH[k][3], bh0, bh1);
                    MMA_BF16(d0, d1, d2, d3, aH[k][0], aH[k][1], aH[k][2], aH[k][3], bl0, bl1);
                    MMA_BF16(d0, d1, d2, d3, aL[k][0], aL[k][1], aL[k][2], aL[k][3], bh0, bh1);
                }
                int j0 = n * 8 + 2 * (lane & 3);
                float c0 = c_s[j0], c1 = c_s[j0 + 1];
                float w0 = w2_s[j0], w1 = w2_s[j0 + 1];
                s0 = fmaf(fmaxf(d0 + c0, 0.f), w0, s0);
                s0 = fmaf(fmaxf(d1 + c1, 0.f), w1, s0);
                s1 = fmaf(fmaxf(d2 + c0, 0.f), w0, s1);
                s1 = fmaf(fmaxf(d3 + c1, 0.f), w1, s1);
            }
            s0 += __shfl_xor_sync(0xffffffffu, s0, 1);
            s0 += __shfl_xor_sync(0xffffffffu, s0, 2);
            s1 += __shfl_xor_sync(0xffffffffu, s1, 1);
            s1 += __shfl_xor_sync(0xffffffffu, s1, 2);
            if ((lane & 3) == 0) {
                int l = mt * 16 + (lane >> 2);
                if (l < HLEN)     sc_s[l]     = s0;
                if (l + 8 < HLEN) sc_s[l + 8] = s1;
            }
        }
    }
    __syncthreads();                                    // sync D

    // ---- S4: fill rows beyond live tiles with s_pad
    {
        float sp = spad_s[0];
        int filled = min(13, (hlen + 15) >> 4) * 16;
        for (int l = filled + tid; l < HLEN; l += NTHREADS) sc_s[l] = sp;
    }
    __syncthreads();                                    // sync E

    // ---- S5: softmax over sc_s[0..199]
    {
        float v = (tid < HLEN) ? sc_s[tid] : -INFINITY;
        float m = v;
        #pragma unroll
        for (int o = 16; o; o >>= 1) m = fmaxf(m, __shfl_xor_sync(0xffffffffu, m, o));
        if (lane == 0) red_s[wid] = m;
        __syncthreads();
        float mm = red_s[0];
        #pragma unroll
        for (int w = 1; w < 8; w++) mm = fmaxf(mm, red_s[w]);

        float e = (tid < HLEN) ? __expf(v - mm) : 0.f;
        float ssum = e;
        #pragma unroll
        for (int o = 16; o; o >>= 1) ssum += __shfl_xor_sync(0xffffffffu, ssum, o);
        if (lane == 0) red_s[8 + wid] = ssum;
        __syncthreads();
        float tot = red_s[8];
        #pragma unroll
        for (int w = 1; w < 8; w++) tot += red_s[8 + w];
        float inv = 1.f / tot;
        if (tid < HLEN) sc_s[tid] = e * inv;
    }
    __syncthreads();

    // ---- S6: pooled[d] = sum_l w[l]*(hi+lo)[l][d]; warp w covers 25 l-rows
    {
        float p0 = 0.f, p1 = 0.f;
        int dp = lane;
        #pragma unroll 5
        for (int i = 0; i < 25; i++) {
            int l = wid * 25 + i;
            float w = sc_s[l];
            int byteoff = l * 128 + (((dp >> 2) ^ (l & 7)) << 4) + (dp & 3) * 4;
            float2 h  = __bfloat1622float2(*(__nv_bfloat162*)(smc + AHI_OFF + byteoff));
            float2 lo = __bfloat1622float2(*(__nv_bfloat162*)(smc + ALO_OFF + byteoff));
            p0 = fmaf(w, h.x + lo.x, p0);
            p1 = fmaf(w, h.y + lo.y, p1);
        }
        red_s[wid * 64 + 2 * dp]     = p0;
        red_s[wid * 64 + 2 * dp + 1] = p1;
    }
    __syncthreads();

    // ---- S7: write comb = [tgt, pooled, pooled - tgt] to global scratch
    if (tid < DIM) {
        float pooled = 0.f;
        #pragma unroll
        for (int w = 0; w < 8; w++) pooled += red_s[w * 64 + tid];
        float tg = tgt_s[tid];
        float* gc = g_comb + (size_t)b * 192;
        gc[tid]        = tg;
        gc[64 + tid]   = pooled;
        gc[128 + tid]  = pooled - tg;
    }
}

// ============================ kernel 2: batched MLP ==========================
// All weights staged in smem once per CTA; 28 rows/CTA -> grid ~147 (1 wave,
// 1 CTA/SM at 177KB smem). Register-tiled: FMA-pipe bound, not LSU.
#define K2_ROWS 28

// smem float offsets
#define S2_W1   0                        // 192x128 = 24576
#define S2_W2   24576                    // 128x64  = 8192
#define S2_W3   32768                    // 64
#define S2_B1   32832                    // 128
#define S2_B2   32960                    // 64
#define S2_CMB  33024                    // 32x192  = 6144 (rows padded to 32)
#define S2_Z1   39168                    // 32x128  = 4096
#define S2_Z2   43264                    // 32x64   = 2048
#define K2_SMEM_FLOATS 45312
#define K2_SMEM_BYTES  (K2_SMEM_FLOATS * 4)

__global__ __launch_bounds__(256, 1)
void mlp_kernel(const float* __restrict__ fW1, const float* __restrict__ fb1,
                const float* __restrict__ fW2, const float* __restrict__ fb2,
                const float* __restrict__ fW3, const float* __restrict__ fb3,
                float* __restrict__ out, int nb)
{
    extern __shared__ float s2[];
    float* W1s = s2 + S2_W1;
    float* W2s = s2 + S2_W2;
    float* W3s = s2 + S2_W3;
    float* B1s = s2 + S2_B1;
    float* B2s = s2 + S2_B2;
    float* Cs  = s2 + S2_CMB;
    float* Z1s = s2 + S2_Z1;
    float* Z2s = s2 + S2_Z2;

    const int tid = threadIdx.x;
    const int r0  = blockIdx.x * K2_ROWS;

    // ---- stage weights + biases + comb rows into smem (coalesced float4)
    for (int i = tid; i < 6144; i += 256) ((float4*)W1s)[i] = __ldg((const float4*)fW1 + i);
    for (int i = tid; i < 2048; i += 256) ((float4*)W2s)[i] = __ldg((const float4*)fW2 + i);
    if (tid < 64)  W3s[tid] = __ldg(fW3 + tid);
    if (tid < 128) B1s[tid] = __ldg(fb1 + tid);
    if (tid < 64)  B2s[tid] = __ldg(fb2 + tid);
    for (int i = tid; i < 32 * 48; i += 256) {
        int row = i / 48;
        int cc  = i - row * 48;
        float4 v = make_float4(0.f, 0.f, 0.f, 0.f);
        if (row < K2_ROWS && r0 + row < nb)
            v = ((const float4*)g_comb)[(size_t)(r0 + row) * 48 + cc];
        ((float4*)Cs)[i] = v;
    }
    __syncthreads();

    // ---- layer 1: z1[r][j] = relu(comb[r].fW1[:,j] + fb1[j])
    // thread = (j: 4 cols, rg: 4 rows). k blocked by 4.
    {
        const int j  = tid & 31;       // cols 4j..4j+3
        const int rg = tid >> 5;       // rows 4rg..4rg+3
        float4 acc0, acc1, acc2, acc3;
        float4 bias = ((const float4*)B1s)[j];
        acc0 = bias; acc1 = bias; acc2 = bias; acc3 = bias;

        const float4* c0p = (const float4*)(Cs + (rg * 4 + 0) * 192);
        const float4* c1p = (const float4*)(Cs + (rg * 4 + 1) * 192);
        const float4* c2p = (const float4*)(Cs + (rg * 4 + 2) * 192);
        const float4* c3p = (const float4*)(Cs + (rg * 4 + 3) * 192);
        const float4* wp  = (const float4*)W1s;

        #pragma unroll 4
        for (int k4 = 0; k4 < 48; k4++) {
            float4 w0 = wp[(k4 * 4 + 0) * 32 + j];
            float4 w1 = wp[(k4 * 4 + 1) * 32 + j];
            float4 w2 = wp[(k4 * 4 + 2) * 32 + j];
            float4 w3 = wp[(k4 * 4 + 3) * 32 + j];
            float4 c0 = c0p[k4], c1 = c1p[k4], c2 = c2p[k4], c3 = c3p[k4];
            #define L1STEP(acc, c) \
                acc.x = fmaf(c.x, w0.x, acc.x); acc.y = fmaf(c.x, w0.y, acc.y); \
                acc.z = fmaf(c.x, w0.z, acc.z); acc.w = fmaf(c.x, w0.w, acc.w); \
                acc.x = fmaf(c.y, w1.x, acc.x); acc.y = fmaf(c.y, w1.y, acc.y); \
                acc.z = fmaf(c.y, w1.z, acc.z); acc.w = fmaf(c.y, w1.w, acc.w); \
                acc.x = fmaf(c.z, w2.x, acc.x); acc.y = fmaf(c.z, w2.y, acc.y); \
                acc.z = fmaf(c.z, w2.z, acc.z); acc.w = fmaf(c.z, w2.w, acc.w); \
                acc.x = fmaf(c.w, w3.x, acc.x); acc.y = fmaf(c.w, w3.y, acc.y); \
                acc.z = fmaf(c.w, w3.z, acc.z); acc.w = fmaf(c.w, w3.w, acc.w);
            L1STEP(acc0, c0)
            L1STEP(acc1, c1)
            L1STEP(acc2, c2)
            L1STEP(acc3, c3)
            #undef L1STEP
        }
        #define RELU4(a) make_float4(fmaxf(a.x,0.f), fmaxf(a.y,0.f), fmaxf(a.z,0.f), fmaxf(a.w,0.f))
        ((float4*)(Z1s + (rg * 4 + 0) * 128))[j] = RELU4(acc0);
        ((float4*)(Z1s + (rg * 4 + 1) * 128))[j] = RELU4(acc1);
        ((float4*)(Z1s + (rg * 4 + 2) * 128))[j] = RELU4(acc2);
        ((float4*)(Z1s + (rg * 4 + 3) * 128))[j] = RELU4(acc3);
    }
    __syncthreads();

    // ---- layer 2: z2[r][j] = relu(z1[r].fW2[:,j] + fb2[j])
    // thread = (j: 4 cols of 64, rg: 2 rows). k blocked by 4 over 128.
    {
        const int j  = tid & 15;       // cols 4j..4j+3
        const int rg = tid >> 4;       // rows 2rg, 2rg+1
        float4 acc0, acc1;
        float4 bias = ((const float4*)B2s)[j];
        acc0 = bias; acc1 = bias;

        const float4* c0p = (const float4*)(Z1s + (rg * 2 + 0) * 128);
        const float4* c1p = (const float4*)(Z1s + (rg * 2 + 1) * 128);
        const float4* wp  = (const float4*)W2s;

        #pragma unroll 4
        for (int k4 = 0; k4 < 32; k4++) {
            float4 w0 = wp[(k4 * 4 + 0) * 16 + j];
            float4 w1 = wp[(k4 * 4 + 1) * 16 + j];
            float4 w2 = wp[(k4 * 4 + 2) * 16 + j];
            float4 w3 = wp[(k4 * 4 + 3) * 16 + j];
            float4 c0 = c0p[k4], c1 = c1p[k4];
            #define L2STEP(acc, c) \
                acc.x = fmaf(c.x, w0.x, acc.x); acc.y = fmaf(c.x, w0.y, acc.y); \
                acc.z = fmaf(c.x, w0.z, acc.z); acc.w = fmaf(c.x, w0.w, acc.w); \
                acc.x = fmaf(c.y, w1.x, acc.x); acc.y = fmaf(c.y, w1.y, acc.y); \
                acc.z = fmaf(c.y, w1.z, acc.z); acc.w = fmaf(c.y, w1.w, acc.w); \
                acc.x = fmaf(c.z, w2.x, acc.x); acc.y = fmaf(c.z, w2.y, acc.y); \
                acc.z = fmaf(c.z, w2.z, acc.z); acc.w = fmaf(c.z, w2.w, acc.w); \
                acc.x = fmaf(c.w, w3.x, acc.x); acc.y = fmaf(c.w, w3.y, acc.y); \
                acc.z = fmaf(c.w, w3.z, acc.z); acc.w = fmaf(c.w, w3.w, acc.w);
            L2STEP(acc0, c0)
            L2STEP(acc1, c1)
            #undef L2STEP
        }
        ((float4*)(Z2s + (rg * 2 + 0) * 64))[j] = RELU4(acc0);
        ((float4*)(Z2s + (rg * 2 + 1) * 64))[j] = RELU4(acc1);
        #undef RELU4
    }
    __syncthreads();

    // ---- layer 3: warp per 4 rows; lanes split the 64-long dot, shuffle-reduce
    {
        const int w    = tid >> 5;
        const int lane = tid & 31;
        float w3a = W3s[lane], w3b = W3s[lane + 32];
        float fb3v = __ldg(fb3);
        #pragma unroll
        for (int rr = 0; rr < 4; rr++) {
            int r = w * 4 + rr;
            const float* zr = Z2s + r * 64;
            float a = fmaf(zr[lane], w3a, zr[lane + 32] * w3b);
            #pragma unroll
            for (int o = 16; o; o >>= 1) a += __shfl_xor_sync(0xffffffffu, a, o);
            if (lane == 0 && r < K2_ROWS && r0 + r < nb)
                out[r0 + r] = 1.f / (1.f + __expf(-(a + fb3v)));
        }
    }
}

extern "C" void kernel_launch(void* const* d_in, const int* in_sizes, int n_in,
                              void* d_out, int out_size)
{
    const int*   item_ids = (const int*)  d_in[0];
    const int*   history  = (const int*)  d_in[1];
    const int*   hist_len = (const int*)  d_in[2];
    const float* emb      = (const float*)d_in[3];
    const float* aW1      = (const float*)d_in[4];
    const float* ab1      = (const float*)d_in[5];
    const float* aW2      = (const float*)d_in[6];
    // d_in[7] = ab2 — dropped (softmax shift-invariant)
    const float* fW1      = (const float*)d_in[8];
    const float* fb1      = (const float*)d_in[9];
    const float* fW2      = (const float*)d_in[10];
    const float* fb2      = (const float*)d_in[11];
    const float* fW3      = (const float*)d_in[12];
    const float* fb3      = (const float*)d_in[13];
    float* out = (float*)d_out;

    const int nb = in_sizes[0];

    cudaFuncSetAttribute(din_kernel, cudaFuncAttributeMaxDynamicSharedMemorySize, SMEM_BYTES);
    din_kernel<<<nb, NTHREADS, SMEM_BYTES>>>(
        item_ids, history, hist_len, emb, aW1, ab1, aW2);

    cudaFuncSetAttribute(mlp_kernel, cudaFuncAttributeMaxDynamicSharedMemorySize, K2_SMEM_BYTES);
    mlp_kernel<<<(nb + K2_ROWS - 1) / K2_ROWS, 256, K2_SMEM_BYTES>>>(
        fW1, fb1, fW2, fb2, fW3, fb3, out, nb);
}

// round 11
// speedup vs baseline: 1.6506x; 1.0375x over previous
#include <cuda_runtime.h>
#include <cuda_bf16.h>
#include <math.h>

#define NTHREADS 256
#define HLEN     200
#define DIM      64
#define MAXB     4096

// ---- K1 dynamic smem layout (bytes) ----
// bf16 tiles: 128B rows, chunk-XOR swizzle: byte(row,chunk)=row*128+((chunk^(row&7))<<4)
#define AHI_OFF   0                      // hist hi: 208 x 64 bf16 = 26624 B
#define ALO_OFF   26624                  // hist lo: 26624 B
#define BHI_OFF   53248                  // M hi: 64 x 64 bf16 = 8192 B
#define BLO_OFF   61440                  // M lo: 8192 B
#define FBASE     69632                  // fp32 region (floats below)
#define F_TGT   (FBASE/4 + 0)            // 64
#define F_C     (F_TGT + 64)             // 64
#define F_W2    (F_C + 64)               // 64
#define F_SC    (F_W2 + 64)              // 200
#define F_RED   (F_SC + 200)             // 512
#define F_HID   (F_RED + 512)            // 200 (int)
#define F_SPAD  (F_HID + 200)            // 1
#define SMEM_FLOATS (F_SPAD + 1)
#define SMEM_BYTES  (SMEM_FLOATS * 4)

// inter-kernel scratch: comb = [tgt, pooled, pooled - tgt] per batch row
__device__ float g_comb[MAXB * 192];

__device__ __forceinline__ unsigned smem_u32(const void* p) {
    unsigned a;
    asm("{ .reg .u64 t; cvta.to.shared.u64 t, %1; cvt.u32.u64 %0, t; }"
        : "=r"(a) : "l"(p));
    return a;
}

#define LDSM_X4(r0, r1, r2, r3, addr) \
    asm volatile("ldmatrix.sync.aligned.m8n8.x4.shared.b16 {%0,%1,%2,%3}, [%4];" \
        : "=r"(r0), "=r"(r1), "=r"(r2), "=r"(r3) : "r"(addr))

#define LDSM_X2T(r0, r1, addr) \
    asm volatile("ldmatrix.sync.aligned.m8n8.x2.trans.shared.b16 {%0,%1}, [%2];" \
        : "=r"(r0), "=r"(r1) : "r"(addr))

#define MMA_BF16(d0, d1, d2, d3, a0, a1, a2, a3, b0, b1) \
    asm volatile("mma.sync.aligned.m16n8k16.row.col.f32.bf16.bf16.f32 " \
        "{%0,%1,%2,%3}, {%4,%5,%6,%7}, {%8,%9}, {%0,%1,%2,%3};" \
        : "+f"(d0), "+f"(d1), "+f"(d2), "+f"(d3) \
        : "r"(a0), "r"(a1), "r"(a2), "r"(a3), "r"(b0), "r"(b1))

__global__ __launch_bounds__(NTHREADS, 3)
void din_kernel(const int*   __restrict__ item_ids,
                const int*   __restrict__ history,
                const int*   __restrict__ hist_len,
                const float* __restrict__ emb,
                const float* __restrict__ aW1,
                const float* __restrict__ ab1,
                const float* __restrict__ aW2)
{
    extern __shared__ float sm[];
    char*  smc    = (char*)sm;
    float* tgt_s  = sm + F_TGT;
    float* c_s    = sm + F_C;
    float* w2_s   = sm + F_W2;
    float* sc_s   = sm + F_SC;
    float* red_s  = sm + F_RED;
    int*   hid_s  = (int*)(sm + F_HID);
    float* spad_s = sm + F_SPAD;

    const int b    = blockIdx.x;
    const int tid  = threadIdx.x;
    const int lane = tid & 31;
    const int wid  = tid >> 5;
    const unsigned sbase = smem_u32(sm);

    // ---- S0: history ids + target embedding + w2
    if (tid < HLEN) hid_s[tid] = history[b * HLEN + tid];
    if (tid < 16) {
        int iid = item_ids[b];
        ((float4*)tgt_s)[tid] = ((const float4*)(emb + (size_t)iid * DIM))[tid];
    }
    if (tid < DIM) w2_s[tid] = __ldg(aW2 + tid);
    __syncthreads();                                    // sync A

    const int hlen = hist_len[b];
    const int nt   = min(13, (hlen + 15) >> 4);   // live m16-tiles
    const int gtot = nt * 16 * 16;                // gather idx bound (rows*16)

    // ---- S1a: coalesced gather -> bf16 hi/lo tiles, ONLY live-tile rows.
    // Rows [hlen, nt*16) zeroed; rows >= nt*16 never touched nor read.
    for (int base = 0; base < gtot; base += 4 * NTHREADS) {
        float4 v[4];
        #pragma unroll
        for (int u = 0; u < 4; u++) {
            int idx = base + u * NTHREADS + tid;
            if (idx < gtot) {
                int row = idx >> 4;
                int c   = idx & 15;
                v[u] = make_float4(0.f, 0.f, 0.f, 0.f);
                if (row < hlen)
                    v[u] = ((const float4*)(emb + (size_t)hid_s[row] * DIM))[c];
            }
        }
        #pragma unroll
        for (int u = 0; u < 4; u++) {
            int idx = base + u * NTHREADS + tid;
            if (idx < gtot) {
                int row = idx >> 4;
                int c   = idx & 15;
                __nv_bfloat162 h01 = __floats2bfloat162_rn(v[u].x, v[u].y);
                __nv_bfloat162 h23 = __floats2bfloat162_rn(v[u].z, v[u].w);
                float lx = v[u].x - __bfloat162float(h01.x);
                float ly = v[u].y - __bfloat162float(h01.y);
                float lz = v[u].z - __bfloat162float(h23.x);
                float lw = v[u].w - __bfloat162float(h23.y);
                __nv_bfloat162 l01 = __floats2bfloat162_rn(lx, ly);
                __nv_bfloat162 l23 = __floats2bfloat162_rn(lz, lw);
                int byteoff = row * 128 + (((c >> 1) ^ (row & 7)) << 4) + (c & 1) * 8;
                uint2 hh = make_uint2(*(unsigned*)&h01, *(unsigned*)&h23);
                uint2 ll = make_uint2(*(unsigned*)&l01, *(unsigned*)&l23);
                *(uint2*)(smc + AHI_OFF + byteoff) = hh;
                *(uint2*)(smc + ALO_OFF + byteoff) = ll;
            }
        }
    }

    // ---- S1b: B tiles (M[d][j] = A1[d][j] + tgt[d]*A3[d][j]) bf16 hi/lo, swizzled.
    {
        int d  = tid >> 2;
        int jq = tid & 3;
        float t = tgt_s[d];
        const float* r1 = aW1 + d * DIM;
        const float* r3 = aW1 + (128 + d) * DIM;
        #pragma unroll
        for (int i = 0; i < 8; i++) {
            int j = jq * 16 + i * 2;
            float m0 = fmaf(t, __ldg(r3 + j),     __ldg(r1 + j));
            float m1 = fmaf(t, __ldg(r3 + j + 1), __ldg(r1 + j + 1));
            __nv_bfloat162 h = __floats2bfloat162_rn(m0, m1);
            float l0f = m0 - __bfloat162float(h.x);
            float l1f = m1 - __bfloat162float(h.y);
            __nv_bfloat162 l = __floats2bfloat162_rn(l0f, l1f);
            int byteoff = d * 128 + ((((jq << 1) + (i >> 2)) ^ (d & 7)) << 4) + (i & 3) * 4;
            *(unsigned*)(smc + BHI_OFF + byteoff) = *(unsigned*)&h;
            *(unsigned*)(smc + BLO_OFF + byteoff) = *(unsigned*)&l;
        }
    }

    // ---- S1c: c_j partials: sum_d tgt[d]*A2[d][j] over 16-d slice
    {
        int jj = tid & 63, g = tid >> 6;
        const float* A2 = aW1 + 64 * DIM;
        float p = 0.f;
        #pragma unroll
        for (int d = g * 16; d < g * 16 + 16; d++)
            p = fmaf(tgt_s[d], __ldg(A2 + d * DIM + jj), p);
        red_s[tid] = p;
    }
    __syncthreads();                                    // sync B

    // ---- S2: finalize c_j; stage relu(c)*w2 for s_pad in red_s[256..319]
    if (tid < DIM) {
        float c = __ldg(ab1 + tid) + red_s[tid] + red_s[64 + tid]
                + red_s[128 + tid] + red_s[192 + tid];
        c_s[tid]         = c;
        red_s[256 + tid] = fmaxf(c, 0.f) * w2_s[tid];
    }
    __syncthreads();                                    // sync C

    // ---- S3a: warp 0 reduces s_pad
    if (wid == 0) {
        float v = red_s[256 + lane] + red_s[288 + lane];
        #pragma unroll
        for (int o = 16; o; o >>= 1) v += __shfl_xor_sync(0xffffffffu, v, o);
        if (lane == 0) spad_s[0] = v;
    }

    // ---- S3b: scores GEMM on tensor pipe (mma.sync bf16, 3-term hi/lo split).
    {
        const int m_off = ((lane >> 3) & 1) * 8 + (lane & 7);
        const int khalf = lane >> 4;
        const int bko   = ((lane >> 3) & 1) * 8 + (lane & 7);

        for (int mt = wid; mt < nt; mt += 8) {
            unsigned aH[4][4], aL[4][4];
            const int r = mt * 16 + m_off;
            #pragma unroll
            for (int k = 0; k < 4; k++) {
                unsigned ad = sbase + AHI_OFF + r * 128 + ((((k << 1) + khalf) ^ (r & 7)) << 4);
                LDSM_X4(aH[k][0], aH[k][1], aH[k][2], aH[k][3], ad);
                LDSM_X4(aL[k][0], aL[k][1], aL[k][2], aL[k][3], ad + (ALO_OFF - AHI_OFF));
            }

            float s0 = 0.f, s1 = 0.f;
            #pragma unroll
            for (int n = 0; n < 8; n++) {
                float d0 = 0.f, d1 = 0.f, d2 = 0.f, d3 = 0.f;
                #pragma unroll
                for (int k = 0; k < 4; k++) {
                    int drow = k * 16 + bko;
                    unsigned bd = sbase + BHI_OFF + drow * 128 + ((n ^ (drow & 7)) << 4);
                    unsigned bh0, bh1, bl0, bl1;
                    LDSM_X2T(bh0, bh1, bd);
                    LDSM_X2T(bl0, bl1, bd + (BLO_OFF - BHI_OFF));
                    MMA_BF16(d0, d1, d2, d3, aH[k][0], aH[k][1], aH[k][2], aH[k][3], bh0, bh1);
                    MMA_BF16(d0, d1, d2, d3, aH[k][0], aH[k][1], aH[k][2], aH[k][3], bl0, bl1);
                    MMA_BF16(d0, d1, d2, d3, aL[k][0], aL[k][1], aL[k][2], aL[k][3], bh0, bh1);
                }
                int j0 = n * 8 + 2 * (lane & 3);
                float c0 = c_s[j0], c1 = c_s[j0 + 1];
                float w0 = w2_s[j0], w1 = w2_s[j0 + 1];
                s0 = fmaf(fmaxf(d0 + c0, 0.f), w0, s0);
                s0 = fmaf(fmaxf(d1 + c1, 0.f), w1, s0);
                s1 = fmaf(fmaxf(d2 + c0, 0.f), w0, s1);
                s1 = fmaf(fmaxf(d3 + c1, 0.f), w1, s1);
            }
            s0 += __shfl_xor_sync(0xffffffffu, s0, 1);
            s0 += __shfl_xor_sync(0xffffffffu, s0, 2);
            s1 += __shfl_xor_sync(0xffffffffu, s1, 1);
            s1 += __shfl_xor_sync(0xffffffffu, s1, 2);
            if ((lane & 3) == 0) {
                int l = mt * 16 + (lane >> 2);
                if (l < HLEN)     sc_s[l]     = s0;
                if (l + 8 < HLEN) sc_s[l + 8] = s1;
            }
        }
    }
    __syncthreads();                                    // sync D

    // ---- S4: fill rows beyond live tiles with s_pad
    {
        float sp = spad_s[0];
        int filled = nt * 16;
        for (int l = filled + tid; l < HLEN; l += NTHREADS) sc_s[l] = sp;
    }
    __syncthreads();                                    // sync E

    // ---- S5: softmax over sc_s[0..199]
    {
        float v = (tid < HLEN) ? sc_s[tid] : -INFINITY;
        float m = v;
        #pragma unroll
        for (int o = 16; o; o >>= 1) m = fmaxf(m, __shfl_xor_sync(0xffffffffu, m, o));
        if (lane == 0) red_s[wid] = m;
        __syncthreads();
        float mm = red_s[0];
        #pragma unroll
        for (int w = 1; w < 8; w++) mm = fmaxf(mm, red_s[w]);

        float e = (tid < HLEN) ? __expf(v - mm) : 0.f;
        float ssum = e;
        #pragma unroll
        for (int o = 16; o; o >>= 1) ssum += __shfl_xor_sync(0xffffffffu, ssum, o);
        if (lane == 0) red_s[8 + wid] = ssum;
        __syncthreads();
        float tot = red_s[8];
        #pragma unroll
        for (int w = 1; w < 8; w++) tot += red_s[8 + w];
        float inv = 1.f / tot;
        if (tid < HLEN) sc_s[tid] = e * inv;
    }
    __syncthreads();

    // ---- S6: pooled[d] = sum_{l<hlen} w[l]*(hi+lo)[l][d]; row-strided warps,
    // early-exit at hlen (pad rows contribute 0 anyway; rows>=nt*16 unwritten).
    {
        float p0 = 0.f, p1 = 0.f;
        int dp = lane;
        for (int l = wid; l < hlen; l += 8) {
            float w = sc_s[l];
            int byteoff = l * 128 + (((dp >> 2) ^ (l & 7)) << 4) + (dp & 3) * 4;
            float2 h  = __bfloat1622float2(*(__nv_bfloat162*)(smc + AHI_OFF + byteoff));
            float2 lo = __bfloat1622float2(*(__nv_bfloat162*)(smc + ALO_OFF + byteoff));
            p0 = fmaf(w, h.x + lo.x, p0);
            p1 = fmaf(w, h.y + lo.y, p1);
        }
        red_s[wid * 64 + 2 * dp]     = p0;
        red_s[wid * 64 + 2 * dp + 1] = p1;
    }
    __syncthreads();

    // ---- S7: write comb = [tgt, pooled, pooled - tgt] to global scratch
    if (tid < DIM) {
        float pooled = 0.f;
        #pragma unroll
        for (int w = 0; w < 8; w++) pooled += red_s[w * 64 + tid];
        float tg = tgt_s[tid];
        float* gc = g_comb + (size_t)b * 192;
        gc[tid]        = tg;
        gc[64 + tid]   = pooled;
        gc[128 + tid]  = pooled - tg;
    }
}

// ============================ kernel 2: batched MLP ==========================
// All weights staged in smem once per CTA; 28 rows/CTA -> grid ~147 (1 wave,
// 1 CTA/SM). Register-tiled: FMA-pipe bound, not LSU.
#define K2_ROWS 28

// smem float offsets
#define S2_W1   0                        // 192x128 = 24576
#define S2_W2   24576                    // 128x64  = 8192
#define S2_W3   32768                    // 64
#define S2_B1   32832                    // 128
#define S2_B2   32960                    // 64
#define S2_CMB  33024                    // 32x192  = 6144 (rows padded to 32)
#define S2_Z1   39168                    // 32x128  = 4096
#define S2_Z2   43264                    // 32x64   = 2048
#define K2_SMEM_FLOATS 45312
#define K2_SMEM_BYTES  (K2_SMEM_FLOATS * 4)

__global__ __launch_bounds__(256, 1)
void mlp_kernel(const float* __restrict__ fW1, const float* __restrict__ fb1,
                const float* __restrict__ fW2, const float* __restrict__ fb2,
                const float* __restrict__ fW3, const float* __restrict__ fb3,
                float* __restrict__ out, int nb)
{
    extern __shared__ float s2[];
    float* W1s = s2 + S2_W1;
    float* W2s = s2 + S2_W2;
    float* W3s = s2 + S2_W3;
    float* B1s = s2 + S2_B1;
    float* B2s = s2 + S2_B2;
    float* Cs  = s2 + S2_CMB;
    float* Z1s = s2 + S2_Z1;
    float* Z2s = s2 + S2_Z2;

    const int tid = threadIdx.x;
    const int r0  = blockIdx.x * K2_ROWS;

    // ---- stage weights + biases + comb rows into smem (coalesced float4)
    for (int i = tid; i < 6144; i += 256) ((float4*)W1s)[i] = __ldg((const float4*)fW1 + i);
    for (int i = tid; i < 2048; i += 256) ((float4*)W2s)[i] = __ldg((const float4*)fW2 + i);
    if (tid < 64)  W3s[tid] = __ldg(fW3 + tid);
    if (tid < 128) B1s[tid] = __ldg(fb1 + tid);
    if (tid < 64)  B2s[tid] = __ldg(fb2 + tid);
    for (int i = tid; i < 32 * 48; i += 256) {
        int row = i / 48;
        int cc  = i - row * 48;
        float4 v = make_float4(0.f, 0.f, 0.f, 0.f);
        if (row < K2_ROWS && r0 + row < nb)
            v = ((const float4*)g_comb)[(size_t)(r0 + row) * 48 + cc];
        ((float4*)Cs)[i] = v;
    }
    __syncthreads();

    // ---- layer 1: z1[r][j] = relu(comb[r].fW1[:,j] + fb1[j])
    {
        const int j  = tid & 31;       // cols 4j..4j+3
        const int rg = tid >> 5;       // rows 4rg..4rg+3
        float4 acc0, acc1, acc2, acc3;
        float4 bias = ((const float4*)B1s)[j];
        acc0 = bias; acc1 = bias; acc2 = bias; acc3 = bias;

        const float4* c0p = (const float4*)(Cs + (rg * 4 + 0) * 192);
        const float4* c1p = (const float4*)(Cs + (rg * 4 + 1) * 192);
        const float4* c2p = (const float4*)(Cs + (rg * 4 + 2) * 192);
        const float4* c3p = (const float4*)(Cs + (rg * 4 + 3) * 192);
        const float4* wp  = (const float4*)W1s;

        #pragma unroll 4
        for (int k4 = 0; k4 < 48; k4++) {
            float4 w0 = wp[(k4 * 4 + 0) * 32 + j];
            float4 w1 = wp[(k4 * 4 + 1) * 32 + j];
            float4 w2 = wp[(k4 * 4 + 2) * 32 + j];
            float4 w3 = wp[(k4 * 4 + 3) * 32 + j];
            float4 c0 = c0p[k4], c1 = c1p[k4], c2 = c2p[k4], c3 = c3p[k4];
            #define L1STEP(acc, c) \
                acc.x = fmaf(c.x, w0.x, acc.x); acc.y = fmaf(c.x, w0.y, acc.y); \
                acc.z = fmaf(c.x, w0.z, acc.z); acc.w = fmaf(c.x, w0.w, acc.w); \
                acc.x = fmaf(c.y, w1.x, acc.x); acc.y = fmaf(c.y, w1.y, acc.y); \
                acc.z = fmaf(c.y, w1.z, acc.z); acc.w = fmaf(c.y, w1.w, acc.w); \
                acc.x = fmaf(c.z, w2.x, acc.x); acc.y = fmaf(c.z, w2.y, acc.y); \
                acc.z = fmaf(c.z, w2.z, acc.z); acc.w = fmaf(c.z, w2.w, acc.w); \
                acc.x = fmaf(c.w, w3.x, acc.x); acc.y = fmaf(c.w, w3.y, acc.y); \
                acc.z = fmaf(c.w, w3.z, acc.z); acc.w = fmaf(c.w, w3.w, acc.w);
            L1STEP(acc0, c0)
            L1STEP(acc1, c1)
            L1STEP(acc2, c2)
            L1STEP(acc3, c3)
            #undef L1STEP
        }
        #define RELU4(a) make_float4(fmaxf(a.x,0.f), fmaxf(a.y,0.f), fmaxf(a.z,0.f), fmaxf(a.w,0.f))
        ((float4*)(Z1s + (rg * 4 + 0) * 128))[j] = RELU4(acc0);
        ((float4*)(Z1s + (rg * 4 + 1) * 128))[j] = RELU4(acc1);
        ((float4*)(Z1s + (rg * 4 + 2) * 128))[j] = RELU4(acc2);
        ((float4*)(Z1s + (rg * 4 + 3) * 128))[j] = RELU4(acc3);
    }
    __syncthreads();

    // ---- layer 2: z2[r][j] = relu(z1[r].fW2[:,j] + fb2[j])
    {
        const int j  = tid & 15;       // cols 4j..4j+3
        const int rg = tid >> 4;       // rows 2rg, 2rg+1
        float4 acc0, acc1;
        float4 bias = ((const float4*)B2s)[j];
        acc0 = bias; acc1 = bias;

        const float4* c0p = (const float4*)(Z1s + (rg * 2 + 0) * 128);
        const float4* c1p = (const float4*)(Z1s + (rg * 2 + 1) * 128);
        const float4* wp  = (const float4*)W2s;

        #pragma unroll 4
        for (int k4 = 0; k4 < 32; k4++) {
            float4 w0 = wp[(k4 * 4 + 0) * 16 + j];
            float4 w1 = wp[(k4 * 4 + 1) * 16 + j];
            float4 w2 = wp[(k4 * 4 + 2) * 16 + j];
            float4 w3 = wp[(k4 * 4 + 3) * 16 + j];
            float4 c0 = c0p[k4], c1 = c1p[k4];
            #define L2STEP(acc, c) \
                acc.x = fmaf(c.x, w0.x, acc.x); acc.y = fmaf(c.x, w0.y, acc.y); \
                acc.z = fmaf(c.x, w0.z, acc.z); acc.w = fmaf(c.x, w0.w, acc.w); \
                acc.x = fmaf(c.y, w1.x, acc.x); acc.y = fmaf(c.y, w1.y, acc.y); \
                acc.z = fmaf(c.y, w1.z, acc.z); acc.w = fmaf(c.y, w1.w, acc.w); \
                acc.x = fmaf(c.z, w2.x, acc.x); acc.y = fmaf(c.z, w2.y, acc.y); \
                acc.z = fmaf(c.z, w2.z, acc.z); acc.w = fmaf(c.z, w2.w, acc.w); \
                acc.x = fmaf(c.w, w3.x, acc.x); acc.y = fmaf(c.w, w3.y, acc.y); \
                acc.z = fmaf(c.w, w3.z, acc.z); acc.w = fmaf(c.w, w3.w, acc.w);
            L2STEP(acc0, c0)
            L2STEP(acc1, c1)
            #undef L2STEP
        }
        ((float4*)(Z2s + (rg * 2 + 0) * 64))[j] = RELU4(acc0);
        ((float4*)(Z2s + (rg * 2 + 1) * 64))[j] = RELU4(acc1);
        #undef RELU4
    }
    __syncthreads();

    // ---- layer 3: warp per 4 rows; lanes split the 64-long dot, shuffle-reduce
    {
        const int w    = tid >> 5;
        const int lane = tid & 31;
        float w3a = W3s[lane], w3b = W3s[lane + 32];
        float fb3v = __ldg(fb3);
        #pragma unroll
        for (int rr = 0; rr < 4; rr++) {
            int r = w * 4 + rr;
            const float* zr = Z2s + r * 64;
            float a = fmaf(zr[lane], w3a, zr[lane + 32] * w3b);
            #pragma unroll
            for (int o = 16; o; o >>= 1) a += __shfl_xor_sync(0xffffffffu, a, o);
            if (lane == 0 && r < K2_ROWS && r0 + r < nb)
                out[r0 + r] = 1.f / (1.f + __expf(-(a + fb3v)));
        }
    }
}

extern "C" void kernel_launch(void* const* d_in, const int* in_sizes, int n_in,
                              void* d_out, int out_size)
{
    const int*   item_ids = (const int*)  d_in[0];
    const int*   history  = (const int*)  d_in[1];
    const int*   hist_len = (const int*)  d_in[2];
    const float* emb      = (const float*)d_in[3];
    const float* aW1      = (const float*)d_in[4];
    const float* ab1      = (const float*)d_in[5];
    const float* aW2      = (const float*)d_in[6];
    // d_in[7] = ab2 — dropped (softmax shift-invariant)
    const float* fW1      = (const float*)d_in[8];
    const float* fb1      = (const float*)d_in[9];
    const float* fW2      = (const float*)d_in[10];
    const float* fb2      = (const float*)d_in[11];
    const float* fW3      = (const float*)d_in[12];
    const float* fb3      = (const float*)d_in[13];
    float* out = (float*)d_out;

    const int nb = in_sizes[0];

    cudaFuncSetAttribute(din_kernel, cudaFuncAttributeMaxDynamicSharedMemorySize, SMEM_BYTES);
    din_kernel<<<nb, NTHREADS, SMEM_BYTES>>>(
        item_ids, history, hist_len, emb, aW1, ab1, aW2);

    cudaFuncSetAttribute(mlp_kernel, cudaFuncAttributeMaxDynamicSharedMemorySize, K2_SMEM_BYTES);
    mlp_kernel<<<(nb + K2_ROWS - 1) / K2_ROWS, 256, K2_SMEM_BYTES>>>(
        fW1, fb1, fW2, fb2, fW3, fb3, out, nb);
}

// round 12
// speedup vs baseline: 3.6051x; 2.1842x over previous
#include <cuda_runtime.h>
#include <cuda_bf16.h>
#include <math.h>

#define NTHREADS 256
#define HLEN     200
#define DIM      64
#define MAXB     4096

// ---- K1 dynamic smem layout ----
// bf16 tiles: 128B rows, chunk-XOR swizzle: byte(row,chunk)=row*128+((chunk^(row&7))<<4)
#define AHI_OFF   0                      // hist hi: 208 x 64 bf16 = 26624 B
#define BHI_OFF   26624                  // M hi: 64(k-rows) x 64 bf16 = 8192 B
#define F_TGT   8704                     // float index; 64
#define F_C     (F_TGT + 64)             // 64
#define F_W2    (F_C + 64)               // 64
#define F_SC    (F_W2 + 64)              // 200
#define F_RED   (F_SC + 200)             // 512
#define F_HID   (F_RED + 512)            // 200 (int)
#define F_SPAD  (F_HID + 200)            // 1
#define SMEM_FLOATS (F_SPAD + 4)
#define SMEM_BYTES  (SMEM_FLOATS * 4)    // ~39.3 KB -> 4 CTAs/SM

// inter-kernel scratch: comb = [tgt, pooled, pooled - tgt] per batch row
__device__ float g_comb[MAXB * 192];

__device__ __forceinline__ unsigned smem_u32(const void* p) {
    unsigned a;
    asm("{ .reg .u64 t; cvta.to.shared.u64 t, %1; cvt.u32.u64 %0, t; }"
        : "=r"(a) : "l"(p));
    return a;
}

#define LDSM_X4(r0, r1, r2, r3, addr) \
    asm volatile("ldmatrix.sync.aligned.m8n8.x4.shared.b16 {%0,%1,%2,%3}, [%4];" \
        : "=r"(r0), "=r"(r1), "=r"(r2), "=r"(r3) : "r"(addr))

#define LDSM_X2T(r0, r1, addr) \
    asm volatile("ldmatrix.sync.aligned.m8n8.x2.trans.shared.b16 {%0,%1}, [%2];" \
        : "=r"(r0), "=r"(r1) : "r"(addr))

#define MMA_BF16(d0, d1, d2, d3, a0, a1, a2, a3, b0, b1) \
    asm volatile("mma.sync.aligned.m16n8k16.row.col.f32.bf16.bf16.f32 " \
        "{%0,%1,%2,%3}, {%4,%5,%6,%7}, {%8,%9}, {%0,%1,%2,%3};" \
        : "+f"(d0), "+f"(d1), "+f"(d2), "+f"(d3) \
        : "r"(a0), "r"(a1), "r"(a2), "r"(a3), "r"(b0), "r"(b1))

__global__ __launch_bounds__(NTHREADS, 4)
void din_kernel(const int*   __restrict__ item_ids,
                const int*   __restrict__ history,
                const int*   __restrict__ hist_len,
                const float* __restrict__ emb,
                const float* __restrict__ aW1,
                const float* __restrict__ ab1,
                const float* __restrict__ aW2)
{
    extern __shared__ float sm[];
    char*  smc    = (char*)sm;
    float* tgt_s  = sm + F_TGT;
    float* c_s    = sm + F_C;
    float* w2_s   = sm + F_W2;
    float* sc_s   = sm + F_SC;
    float* red_s  = sm + F_RED;
    int*   hid_s  = (int*)(sm + F_HID);
    float* spad_s = sm + F_SPAD;

    const int b    = blockIdx.x;
    const int tid  = threadIdx.x;
    const int lane = tid & 31;
    const int wid  = tid >> 5;
    const unsigned sbase = smem_u32(sm);

    // ---- S0: history ids + target embedding + w2
    if (tid < HLEN) hid_s[tid] = history[b * HLEN + tid];
    if (tid < 16) {
        int iid = item_ids[b];
        ((float4*)tgt_s)[tid] = ((const float4*)(emb + (size_t)iid * DIM))[tid];
    }
    if (tid < DIM) w2_s[tid] = __ldg(aW2 + tid);
    __syncthreads();                                    // sync A

    const int hlen = hist_len[b];
    const int nt   = min(13, (hlen + 15) >> 4);   // live m16-tiles
    const int gtot = nt * 256;                    // rows*16 float4 chunks

    // ---- S1a: coalesced gather -> single bf16 hi tile (live rows only).
    for (int base = 0; base < gtot; base += 4 * NTHREADS) {
        float4 v[4];
        #pragma unroll
        for (int u = 0; u < 4; u++) {
            int idx = base + u * NTHREADS + tid;
            if (idx < gtot) {
                int row = idx >> 4;
                int c   = idx & 15;
                v[u] = make_float4(0.f, 0.f, 0.f, 0.f);
                if (row < hlen)
                    v[u] = ((const float4*)(emb + (size_t)hid_s[row] * DIM))[c];
            }
        }
        #pragma unroll
        for (int u = 0; u < 4; u++) {
            int idx = base + u * NTHREADS + tid;
            if (idx < gtot) {
                int row = idx >> 4;
                int c   = idx & 15;
                __nv_bfloat162 h01 = __floats2bfloat162_rn(v[u].x, v[u].y);
                __nv_bfloat162 h23 = __floats2bfloat162_rn(v[u].z, v[u].w);
                int byteoff = row * 128 + (((c >> 1) ^ (row & 7)) << 4) + (c & 1) * 8;
                *(uint2*)(smc + AHI_OFF + byteoff) =
                    make_uint2(*(unsigned*)&h01, *(unsigned*)&h23);
            }
        }
    }

    // ---- S1b: B tile (M[d][j] = A1[d][j] + tgt[d]*A3[d][j]) bf16, COALESCED,
    //           fused with c_j partials (sum_d tgt[d]*A2[d][j]).
    // thread = (jp = tid&31 -> j pair 2jp,2jp+1 ; g8 = tid>>5 -> 8-d slice)
    {
        const int jp = tid & 31;
        const int g8 = tid >> 5;
        const int j0 = jp * 2;
        float p0 = 0.f, p1 = 0.f;
        #pragma unroll
        for (int d = g8 * 8; d < g8 * 8 + 8; d++) {
            float t = tgt_s[d];
            float2 a1 = __ldg((const float2*)(aW1 + d * DIM + j0));
            float2 a2 = __ldg((const float2*)(aW1 + (64 + d) * DIM + j0));
            float2 a3 = __ldg((const float2*)(aW1 + (128 + d) * DIM + j0));
            float m0 = fmaf(t, a3.x, a1.x);
            float m1 = fmaf(t, a3.y, a1.y);
            p0 = fmaf(t, a2.x, p0);
            p1 = fmaf(t, a2.y, p1);
            __nv_bfloat162 h = __floats2bfloat162_rn(m0, m1);
            // B row = d (k-major), cols j: byte = d*128 + swz(j>>3) + (j&7)*2
            int byteoff = d * 128 + ((((unsigned)j0 >> 3) ^ (d & 7)) << 4) + (j0 & 7) * 2;
            *(unsigned*)(smc + BHI_OFF + byteoff) = *(unsigned*)&h;
        }
        red_s[g8 * 64 + j0]     = p0;
        red_s[g8 * 64 + j0 + 1] = p1;
    }
    __syncthreads();                                    // sync B

    // ---- S2: finalize c_j; stage relu(c)*w2 for s_pad in red_s[256..319]
    if (tid < DIM) {
        float c = __ldg(ab1 + tid);
        #pragma unroll
        for (int g = 0; g < 8; g++) c += red_s[g * 64 + tid];
        c_s[tid]         = c;
        red_s[256 + tid] = fmaxf(c, 0.f) * w2_s[tid];
    }
    __syncthreads();                                    // sync C

    // ---- S3a: warp 0 reduces s_pad
    if (wid == 0) {
        float v = red_s[256 + lane] + red_s[288 + lane];
        #pragma unroll
        for (int o = 16; o; o >>= 1) v += __shfl_xor_sync(0xffffffffu, v, o);
        if (lane == 0) spad_s[0] = v;
    }

    // ---- S3b: scores GEMM on tensor pipe (single bf16 term).
    {
        const int m_off = ((lane >> 3) & 1) * 8 + (lane & 7);
        const int khalf = lane >> 4;
        const int bko   = ((lane >> 3) & 1) * 8 + (lane & 7);

        for (int mt = wid; mt < nt; mt += 8) {
            unsigned aH[4][4];
            const int r = mt * 16 + m_off;
            #pragma unroll
            for (int k = 0; k < 4; k++) {
                unsigned ad = sbase + AHI_OFF + r * 128 + ((((k << 1) + khalf) ^ (r & 7)) << 4);
                LDSM_X4(aH[k][0], aH[k][1], aH[k][2], aH[k][3], ad);
            }

            float s0 = 0.f, s1 = 0.f;
            #pragma unroll
            for (int n = 0; n < 8; n++) {
                float d0 = 0.f, d1 = 0.f, d2 = 0.f, d3 = 0.f;
                #pragma unroll
                for (int k = 0; k < 4; k++) {
                    int drow = k * 16 + bko;
                    unsigned bd = sbase + BHI_OFF + drow * 128 + ((n ^ (drow & 7)) << 4);
                    unsigned bh0, bh1;
                    LDSM_X2T(bh0, bh1, bd);
                    MMA_BF16(d0, d1, d2, d3, aH[k][0], aH[k][1], aH[k][2], aH[k][3], bh0, bh1);
                }
                int j0 = n * 8 + 2 * (lane & 3);
                float c0 = c_s[j0], c1 = c_s[j0 + 1];
                float w0 = w2_s[j0], w1 = w2_s[j0 + 1];
                s0 = fmaf(fmaxf(d0 + c0, 0.f), w0, s0);
                s0 = fmaf(fmaxf(d1 + c1, 0.f), w1, s0);
                s1 = fmaf(fmaxf(d2 + c0, 0.f), w0, s1);
                s1 = fmaf(fmaxf(d3 + c1, 0.f), w1, s1);
            }
            s0 += __shfl_xor_sync(0xffffffffu, s0, 1);
            s0 += __shfl_xor_sync(0xffffffffu, s0, 2);
            s1 += __shfl_xor_sync(0xffffffffu, s1, 1);
            s1 += __shfl_xor_sync(0xffffffffu, s1, 2);
            if ((lane & 3) == 0) {
                int l = mt * 16 + (lane >> 2);
                if (l < HLEN)     sc_s[l]     = s0;
                if (l + 8 < HLEN) sc_s[l + 8] = s1;
            }
        }
    }
    __syncthreads();                                    // sync D

    // ---- S4: fill rows beyond live tiles with s_pad
    {
        float sp = spad_s[0];
        int filled = nt * 16;
        for (int l = filled + tid; l < HLEN; l += NTHREADS) sc_s[l] = sp;
    }
    __syncthreads();                                    // sync E

    // ---- S5: softmax over sc_s[0..199]
    {
        float v = (tid < HLEN) ? sc_s[tid] : -INFINITY;
        float m = v;
        #pragma unroll
        for (int o = 16; o; o >>= 1) m = fmaxf(m, __shfl_xor_sync(0xffffffffu, m, o));
        if (lane == 0) red_s[wid] = m;
        __syncthreads();
        float mm = red_s[0];
        #pragma unroll
        for (int w = 1; w < 8; w++) mm = fmaxf(mm, red_s[w]);

        float e = (tid < HLEN) ? __expf(v - mm) : 0.f;
        float ssum = e;
        #pragma unroll
        for (int o = 16; o; o >>= 1) ssum += __shfl_xor_sync(0xffffffffu, ssum, o);
        if (lane == 0) red_s[8 + wid] = ssum;
        __syncthreads();
        float tot = red_s[8];
        #pragma unroll
        for (int w = 1; w < 8; w++) tot += red_s[8 + w];
        float inv = 1.f / tot;
        if (tid < HLEN) sc_s[tid] = e * inv;
    }
    __syncthreads();

    // ---- S6: pooled[d] = sum_{l<hlen} w[l]*emb[hid[l]][d] — EXACT fp32 from L2.
    // warp w: rows l = w, w+8, ...; lane dp: d = 2dp, 2dp+1 (coalesced 256B/row)
    {
        float p0 = 0.f, p1 = 0.f;
        const int dp = lane;
        for (int l = wid; l < hlen; l += 8) {
            float w = sc_s[l];
            float2 hv = __ldg((const float2*)(emb + (size_t)hid_s[l] * DIM) + dp);
            p0 = fmaf(w, hv.x, p0);
            p1 = fmaf(w, hv.y, p1);
        }
        red_s[wid * 64 + 2 * dp]     = p0;
        red_s[wid * 64 + 2 * dp + 1] = p1;
    }
    __syncthreads();

    // ---- S7: write comb = [tgt, pooled, pooled - tgt] to global scratch
    if (tid < DIM) {
        float pooled = 0.f;
        #pragma unroll
        for (int w = 0; w < 8; w++) pooled += red_s[w * 64 + tid];
        float tg = tgt_s[tid];
        float* gc = g_comb + (size_t)b * 192;
        gc[tid]        = tg;
        gc[64 + tid]   = pooled;
        gc[128 + tid]  = pooled - tg;
    }
}

// ============================ kernel 2: batched MLP ==========================
#define K2_ROWS 28

#define S2_W1   0                        // 192x128 = 24576
#define S2_W2   24576                    // 128x64  = 8192
#define S2_W3   32768                    // 64
#define S2_B1   32832                    // 128
#define S2_B2   32960                    // 64
#define S2_CMB  33024                    // 32x192  = 6144 (rows padded to 32)
#define S2_Z1   39168                    // 32x128  = 4096
#define S2_Z2   43264                    // 32x64   = 2048
#define K2_SMEM_FLOATS 45312
#define K2_SMEM_BYTES  (K2_SMEM_FLOATS * 4)

__global__ __launch_bounds__(256, 1)
void mlp_kernel(const float* __restrict__ fW1, const float* __restrict__ fb1,
                const float* __restrict__ fW2, const float* __restrict__ fb2,
                const float* __restrict__ fW3, const float* __restrict__ fb3,
                float* __restrict__ out, int nb)
{
    extern __shared__ float s2[];
    float* W1s = s2 + S2_W1;
    float* W2s = s2 + S2_W2;
    float* W3s = s2 + S2_W3;
    float* B1s = s2 + S2_B1;
    float* B2s = s2 + S2_B2;
    float* Cs  = s2 + S2_CMB;
    float* Z1s = s2 + S2_Z1;
    float* Z2s = s2 + S2_Z2;

    const int tid = threadIdx.x;
    const int r0  = blockIdx.x * K2_ROWS;

    for (int i = tid; i < 6144; i += 256) ((float4*)W1s)[i] = __ldg((const float4*)fW1 + i);
    for (int i = tid; i < 2048; i += 256) ((float4*)W2s)[i] = __ldg((const float4*)fW2 + i);
    if (tid < 64)  W3s[tid] = __ldg(fW3 + tid);
    if (tid < 128) B1s[tid] = __ldg(fb1 + tid);
    if (tid < 64)  B2s[tid] = __ldg(fb2 + tid);
    for (int i = tid; i < 32 * 48; i += 256) {
        int row = i / 48;
        int cc  = i - row * 48;
        float4 v = make_float4(0.f, 0.f, 0.f, 0.f);
        if (row < K2_ROWS && r0 + row < nb)
            v = ((const float4*)g_comb)[(size_t)(r0 + row) * 48 + cc];
        ((float4*)Cs)[i] = v;
    }
    __syncthreads();

    {
        const int j  = tid & 31;
        const int rg = tid >> 5;
        float4 acc0, acc1, acc2, acc3;
        float4 bias = ((const float4*)B1s)[j];
        acc0 = bias; acc1 = bias; acc2 = bias; acc3 = bias;

        const float4* c0p = (const float4*)(Cs + (rg * 4 + 0) * 192);
        const float4* c1p = (const float4*)(Cs + (rg * 4 + 1) * 192);
        const float4* c2p = (const float4*)(Cs + (rg * 4 + 2) * 192);
        const float4* c3p = (const float4*)(Cs + (rg * 4 + 3) * 192);
        const float4* wp  = (const float4*)W1s;

        #pragma unroll 4
        for (int k4 = 0; k4 < 48; k4++) {
            float4 w0 = wp[(k4 * 4 + 0) * 32 + j];
            float4 w1 = wp[(k4 * 4 + 1) * 32 + j];
            float4 w2 = wp[(k4 * 4 + 2) * 32 + j];
            float4 w3 = wp[(k4 * 4 + 3) * 32 + j];
            float4 c0 = c0p[k4], c1 = c1p[k4], c2 = c2p[k4], c3 = c3p[k4];
            #define L1STEP(acc, c) \
                acc.x = fmaf(c.x, w0.x, acc.x); acc.y = fmaf(c.x, w0.y, acc.y); \
                acc.z = fmaf(c.x, w0.z, acc.z); acc.w = fmaf(c.x, w0.w, acc.w); \
                acc.x = fmaf(c.y, w1.x, acc.x); acc.y = fmaf(c.y, w1.y, acc.y); \
                acc.z = fmaf(c.y, w1.z, acc.z); acc.w = fmaf(c.y, w1.w, acc.w); \
                acc.x = fmaf(c.z, w2.x, acc.x); acc.y = fmaf(c.z, w2.y, acc.y); \
                acc.z = fmaf(c.z, w2.z, acc.z); acc.w = fmaf(c.z, w2.w, acc.w); \
                acc.x = fmaf(c.w, w3.x, acc.x); acc.y = fmaf(c.w, w3.y, acc.y); \
                acc.z = fmaf(c.w, w3.z, acc.z); acc.w = fmaf(c.w, w3.w, acc.w);
            L1STEP(acc0, c0)
            L1STEP(acc1, c1)
            L1STEP(acc2, c2)
            L1STEP(acc3, c3)
            #undef L1STEP
        }
        #define RELU4(a) make_float4(fmaxf(a.x,0.f), fmaxf(a.y,0.f), fmaxf(a.z,0.f), fmaxf(a.w,0.f))
        ((float4*)(Z1s + (rg * 4 + 0) * 128))[j] = RELU4(acc0);
        ((float4*)(Z1s + (rg * 4 + 1) * 128))[j] = RELU4(acc1);
        ((float4*)(Z1s + (rg * 4 + 2) * 128))[j] = RELU4(acc2);
        ((float4*)(Z1s + (rg * 4 + 3) * 128))[j] = RELU4(acc3);
    }
    __syncthreads();

    {
        const int j  = tid & 15;
        const int rg = tid >> 4;
        float4 acc0, acc1;
        float4 bias = ((const float4*)B2s)[j];
        acc0 = bias; acc1 = bias;

        const float4* c0p = (const float4*)(Z1s + (rg * 2 + 0) * 128);
        const float4* c1p = (const float4*)(Z1s + (rg * 2 + 1) * 128);
        const float4* wp  = (const float4*)W2s;

        #pragma unroll 4
        for (int k4 = 0; k4 < 32; k4++) {
            float4 w0 = wp[(k4 * 4 + 0) * 16 + j];
            float4 w1 = wp[(k4 * 4 + 1) * 16 + j];
            float4 w2 = wp[(k4 * 4 + 2) * 16 + j];
            float4 w3 = wp[(k4 * 4 + 3) * 16 + j];
            float4 c0 = c0p[k4], c1 = c1p[k4];
            #define L2STEP(acc, c) \
                acc.x = fmaf(c.x, w0.x, acc.x); acc.y = fmaf(c.x, w0.y, acc.y); \
                acc.z = fmaf(c.x, w0.z, acc.z); acc.w = fmaf(c.x, w0.w, acc.w); \
                acc.x = fmaf(c.y, w1.x, acc.x); acc.y = fmaf(c.y, w1.y, acc.y); \
                acc.z = fmaf(c.y, w1.z, acc.z); acc.w = fmaf(c.y, w1.w, acc.w); \
                acc.x = fmaf(c.z, w2.x, acc.x); acc.y = fmaf(c.z, w2.y, acc.y); \
                acc.z = fmaf(c.z, w2.z, acc.z); acc.w = fmaf(c.z, w2.w, acc.w); \
                acc.x = fmaf(c.w, w3.x, acc.x); acc.y = fmaf(c.w, w3.y, acc.y); \
                acc.z = fmaf(c.w, w3.z, acc.z); acc.w = fmaf(c.w, w3.w, acc.w);
            L2STEP(acc0, c0)
            L2STEP(acc1, c1)
            #undef L2STEP
        }
        ((float4*)(Z2s + (rg * 2 + 0) * 64))[j] = RELU4(acc0);
        ((float4*)(Z2s + (rg * 2 + 1) * 64))[j] = RELU4(acc1);
        #undef RELU4
    }
    __syncthreads();

    {
        const int w    = tid >> 5;
        const int lane = tid & 31;
        float w3a = W3s[lane], w3b = W3s[lane + 32];
        float fb3v = __ldg(fb3);
        #pragma unroll
        for (int rr = 0; rr < 4; rr++) {
            int r = w * 4 + rr;
            const float* zr = Z2s + r * 64;
            float a = fmaf(zr[lane], w3a, zr[lane + 32] * w3b);
            #pragma unroll
            for (int o = 16; o; o >>= 1) a += __shfl_xor_sync(0xffffffffu, a, o);
            if (lane == 0 && r < K2_ROWS && r0 + r < nb)
                out[r0 + r] = 1.f / (1.f + __expf(-(a + fb3v)));
        }
    }
}

extern "C" void kernel_launch(void* const* d_in, const int* in_sizes, int n_in,
                              void* d_out, int out_size)
{
    const int*   item_ids = (const int*)  d_in[0];
    const int*   history  = (const int*)  d_in[1];
    const int*   hist_len = (const int*)  d_in[2];
    const float* emb      = (const float*)d_in[3];
    const float* aW1      = (const float*)d_in[4];
    const float* ab1      = (const float*)d_in[5];
    const float* aW2      = (const float*)d_in[6];
    // d_in[7] = ab2 — dropped (softmax shift-invariant)
    const float* fW1      = (const float*)d_in[8];
    const float* fb1      = (const float*)d_in[9];
    const float* fW2      = (const float*)d_in[10];
    const float* fb2      = (const float*)d_in[11];
    const float* fW3      = (const float*)d_in[12];
    const float* fb3      = (const float*)d_in[13];
    float* out = (float*)d_out;

    const int nb = in_sizes[0];

    cudaFuncSetAttribute(din_kernel, cudaFuncAttributeMaxDynamicSharedMemorySize, SMEM_BYTES);
    din_kernel<<<nb, NTHREADS, SMEM_BYTES>>>(
        item_ids, history, hist_len, emb, aW1, ab1, aW2);

    cudaFuncSetAttribute(mlp_kernel, cudaFuncAttributeMaxDynamicSharedMemorySize, K2_SMEM_BYTES);
    mlp_kernel<<<(nb + K2_ROWS - 1) / K2_ROWS, 256, K2_SMEM_BYTES>>>(
        fW1, fb1, fW2, fb2, fW3, fb3, out, nb);
}